// round 13
// baseline (speedup 1.0000x reference)
#include <cuda_runtime.h>
#include <cuda_bf16.h>
#include <math.h>
#include <stdint.h>

#define NPTS   131072
#define PB     16384
#define BATCH  8
#define MTOK   128
#define KNN    16
#define TOKD   768
#define NGATH  (BATCH*MTOK*KNN)   // 16384 gathered neighbor rows
#define KSEL   256                // candidate pool per batch
#define NCAND  (BATCH*KSEL)       // 2048

// ---------------- scratch (device globals; no allocs allowed) ----------------
__device__ __align__(16) float g_x8[NPTS*8];
__device__ __align__(16) float g_w1p[8*256];
__device__ __align__(16) float g_c4[NPTS*4];
__device__ __align__(16) __nv_bfloat16 g_h1h[(size_t)NPTS*256], g_h1l[(size_t)NPTS*256];
__device__ __align__(16) __nv_bfloat16 g_h2h[(size_t)NPTS*512];
__device__ __align__(16) __nv_bfloat16 g_h3h[(size_t)NPTS*768];
__device__ __align__(16) float g_wp[768*256];          // w4 @ iw1[0:768]
__device__ __align__(16) float g_biasp[256];
__device__ __align__(16) float g_zero256[256];         // stays zero
__device__ __align__(16) float g_rb[(size_t)NPTS*256]; // c4 @ iw1[768:772]
__device__ __align__(16) float g_z1[(size_t)NPTS*256];
__device__ __align__(16) __nv_bfloat16 g_z2h[(size_t)NPTS*256], g_z2l[(size_t)NPTS*256];
__device__ __align__(16) float g_z3[(size_t)NPTS*256];
__device__ float g_imp[NPTS];
// split weights [N][K] bf16 hi/lo
__device__ __align__(16) __nv_bfloat16 g_w2th[512*256],  g_w2tl[512*256];
__device__ __align__(16) __nv_bfloat16 g_w3th[768*512],  g_w3tl[768*512];
__device__ __align__(16) __nv_bfloat16 g_w4th[768*768],  g_w4tl[768*768];
__device__ __align__(16) __nv_bfloat16 g_wpth[256*768],  g_wptl[256*768];
__device__ __align__(16) __nv_bfloat16 g_iw2th[256*256], g_iw2tl[256*256];
// refinement
__device__ int   g_cand[NCAND];
__device__ __align__(16) float g_xc[NCAND*8];
__device__ __align__(16) float g_rbc[NCAND*256];
__device__ __align__(16) float g_h1c[NCAND*256];
__device__ __align__(16) float g_h2c[NCAND*512];
__device__ __align__(16) float g_h3c[NCAND*768];
__device__ __align__(16) float g_z1c[NCAND*256];
__device__ __align__(16) float g_z2c[NCAND*256];
__device__ __align__(16) float g_z3c[NCAND*256];
__device__ float g_impc[NCAND];
// selection + neighbor recompute
__device__ float g_cent[BATCH*MTOK*4];
__device__ int   g_order[BATCH*MTOK];
__device__ int   g_knn[BATCH*MTOK*KNN];
__device__ __align__(16) float g_gx[NGATH*8];
__device__ __align__(16) __nv_bfloat16 g_h1gh[(size_t)NGATH*256], g_h1gl[(size_t)NGATH*256];
__device__ __align__(16) __nv_bfloat16 g_h2gh[(size_t)NGATH*512], g_h2gl[(size_t)NGATH*512];
__device__ __align__(16) __nv_bfloat16 g_gh[(size_t)NGATH*768], g_gl[(size_t)NGATH*768];
__device__ __align__(16) float g_pfg[(size_t)NGATH*768];
__device__ __align__(16) float g_pooled[BATCH*MTOK*TOKD];
__device__ __align__(16) float g_t1[BATCH*MTOK*TOKD];
__device__ __align__(16) float g_tok[BATCH*MTOK*TOKD];

__device__ __forceinline__ unsigned packbf(float lo, float hi){
    unsigned r; asm("cvt.rn.bf16x2.f32 %0, %2, %1;" : "=r"(r) : "f"(lo), "f"(hi)); return r;
}
__device__ __forceinline__ unsigned f2u(float x){
    unsigned u = __float_as_uint(x);
    return (u & 0x80000000u) ? ~u : (u | 0x80000000u);
}
__device__ __forceinline__ void cp16(uint32_t saddr, const void* gptr){
    asm volatile("cp.async.ca.shared.global [%0], [%1], 16;" :: "r"(saddr), "l"(gptr) : "memory");
}
#define CP_COMMIT() asm volatile("cp.async.commit_group;" ::: "memory")
#define CP_WAIT0()  asm volatile("cp.async.wait_group 0;" ::: "memory")

// ---------------- prep -------------------------------------------------------
__global__ void prep_points(const float* __restrict__ coords,
                            const float* __restrict__ feats)
{
    int i = blockIdx.x*blockDim.x + threadIdx.x;
    if (i >= NPTS) return;
    #pragma unroll
    for (int j=0;j<6;j++) g_x8[i*8+j] = feats[i*6+j];
    g_x8[i*8+6]=0.f; g_x8[i*8+7]=0.f;
    #pragma unroll
    for (int j=0;j<4;j++) g_c4[i*4+j] = coords[i*5+1+j];
}
__global__ void prep_w(const float* __restrict__ w1)
{
    int idx = blockIdx.x*blockDim.x + threadIdx.x;
    if (idx < 8*256) g_w1p[idx] = (idx < 6*256) ? w1[idx] : 0.f;
}
__global__ void biasp_init(const float* __restrict__ ib1, float* __restrict__ bp)
{ bp[threadIdx.x] = ib1[threadIdx.x]; }
__global__ void biasp_acc(const float* __restrict__ b4, const float* __restrict__ iw1,
                          float* __restrict__ bp)
{
    int n = threadIdx.x;
    int j0 = blockIdx.x*96;
    float s = 0.f;
    for (int j=j0;j<j0+96;j++) s += b4[j]*iw1[(size_t)j*256+n];
    atomicAdd(&bp[n], s);
}
__global__ void rb_kernel(const float* __restrict__ c4, const float* __restrict__ iw1,
                          float* __restrict__ rb)
{
    int tid = threadIdx.x;
    int i   = blockIdx.x*4 + (tid>>6);
    int n   = (tid & 63)*4;
    float4 c  = *(const float4*)(c4 + (size_t)i*4);
    float4 r0 = *(const float4*)(iw1 + (size_t)768*256 + n);
    float4 r1 = *(const float4*)(iw1 + (size_t)769*256 + n);
    float4 r2 = *(const float4*)(iw1 + (size_t)770*256 + n);
    float4 r3 = *(const float4*)(iw1 + (size_t)771*256 + n);
    float4 o;
    o.x = c.x*r0.x + c.y*r1.x + c.z*r2.x + c.w*r3.x;
    o.y = c.x*r0.y + c.y*r1.y + c.z*r2.y + c.w*r3.y;
    o.z = c.x*r0.z + c.y*r1.z + c.z*r2.z + c.w*r3.z;
    o.w = c.x*r0.w + c.y*r1.w + c.z*r2.w + c.w*r3.w;
    *(float4*)(rb + (size_t)i*256 + n) = o;
}
__global__ void conv_wt(const float* __restrict__ src, int K, int N,
                        __nv_bfloat16* __restrict__ dh, __nv_bfloat16* __restrict__ dl)
{
    int idx = blockIdx.x*blockDim.x + threadIdx.x;
    if (idx >= N*K) return;
    int n = idx / K, k = idx - n*K;
    float v = src[(size_t)k*N + n];
    __nv_bfloat16 h = __float2bfloat16(v);
    dh[idx] = h;
    dl[idx] = __float2bfloat16(v - __bfloat162float(h));
}

// ---------------- scalar SGEMM (proven core) ---------------------------------
template<bool RELU, bool RB, int OM>
__global__ __launch_bounds__(256,2) void sgemm128(
    const float* __restrict__ A, int lda,
    const float* __restrict__ B, int N,
    const float* __restrict__ bias,
    const float* __restrict__ rowbias,
    float* __restrict__ C,
    __nv_bfloat16* __restrict__ Chi, __nv_bfloat16* __restrict__ Clo,
    int ldc, int K)
{
    __shared__ float As[2][8][128];
    __shared__ float Bs[2][8][128];
    const int tid  = threadIdx.x;
    const int bm   = blockIdx.y * 128;
    const int bn   = blockIdx.x * 128;
    const int arow = tid >> 1;
    const int acol = (tid & 1) * 4;
    const int brow = tid >> 5;
    const int bcol = (tid & 31) * 4;
    const int tx   = tid & 15;
    const int ty   = tid >> 4;

    const float* Aptr = A + (size_t)(bm + arow) * lda + acol;
    const float* Bptr = B + (size_t)brow * N + bn + bcol;

    float acc[8][8];
    #pragma unroll
    for (int i=0;i<8;i++)
        #pragma unroll
        for (int j=0;j<8;j++) acc[i][j]=0.f;

    {
        float4 a = *(const float4*)Aptr;
        As[0][acol+0][arow]=a.x; As[0][acol+1][arow]=a.y;
        As[0][acol+2][arow]=a.z; As[0][acol+3][arow]=a.w;
        *(float4*)&Bs[0][brow][bcol] = *(const float4*)Bptr;
    }
    __syncthreads();

    const int ktiles = K >> 3;
    int buf = 0;
    for (int kt=0; kt<ktiles; kt++){
        float4 a, bv;
        const bool has = (kt+1 < ktiles);
        if (has){
            a  = *(const float4*)(Aptr + (kt+1)*8);
            bv = *(const float4*)(Bptr + (size_t)(kt+1)*8*N);
        }
        #pragma unroll
        for (int k=0;k<8;k++){
            float4 a0 = *(const float4*)&As[buf][k][ty*4];
            float4 a1 = *(const float4*)&As[buf][k][64+ty*4];
            float4 b0 = *(const float4*)&Bs[buf][k][tx*4];
            float4 b1 = *(const float4*)&Bs[buf][k][64+tx*4];
            float ar[8] = {a0.x,a0.y,a0.z,a0.w,a1.x,a1.y,a1.z,a1.w};
            float br[8] = {b0.x,b0.y,b0.z,b0.w,b1.x,b1.y,b1.z,b1.w};
            #pragma unroll
            for (int i=0;i<8;i++)
                #pragma unroll
                for (int j=0;j<8;j++)
                    acc[i][j] += ar[i]*br[j];
        }
        if (has){
            const int nb = buf^1;
            As[nb][acol+0][arow]=a.x; As[nb][acol+1][arow]=a.y;
            As[nb][acol+2][arow]=a.z; As[nb][acol+3][arow]=a.w;
            *(float4*)&Bs[nb][brow][bcol] = bv;
        }
        __syncthreads();
        buf ^= 1;
    }

    float4 bv0 = *(const float4*)(bias + bn + tx*4);
    float4 bv1 = *(const float4*)(bias + bn + 64 + tx*4);
    #pragma unroll
    for (int i=0;i<8;i++){
        const int row = bm + ((i<4) ? (ty*4+i) : (64 + ty*4 + i - 4));
        float4 o0, o1;
        o0.x=acc[i][0]+bv0.x; o0.y=acc[i][1]+bv0.y; o0.z=acc[i][2]+bv0.z; o0.w=acc[i][3]+bv0.w;
        o1.x=acc[i][4]+bv1.x; o1.y=acc[i][5]+bv1.y; o1.z=acc[i][6]+bv1.z; o1.w=acc[i][7]+bv1.w;
        if (RB){
            float4 r0 = *(const float4*)(rowbias + (size_t)row*ldc + bn + tx*4);
            float4 r1 = *(const float4*)(rowbias + (size_t)row*ldc + bn + 64 + tx*4);
            o0.x+=r0.x; o0.y+=r0.y; o0.z+=r0.z; o0.w+=r0.w;
            o1.x+=r1.x; o1.y+=r1.y; o1.z+=r1.z; o1.w+=r1.w;
        }
        if (RELU){
            o0.x=fmaxf(o0.x,0.f); o0.y=fmaxf(o0.y,0.f); o0.z=fmaxf(o0.z,0.f); o0.w=fmaxf(o0.w,0.f);
            o1.x=fmaxf(o1.x,0.f); o1.y=fmaxf(o1.y,0.f); o1.z=fmaxf(o1.z,0.f); o1.w=fmaxf(o1.w,0.f);
        }
        if (OM == 0){
            *(float4*)(C + (size_t)row*ldc + bn + tx*4)      = o0;
            *(float4*)(C + (size_t)row*ldc + bn + 64 + tx*4) = o1;
        } else {
            float v[8] = {o0.x,o0.y,o0.z,o0.w,o1.x,o1.y,o1.z,o1.w};
            float h[8], l[8];
            #pragma unroll
            for (int q=0;q<8;q++){
                __nv_bfloat16 hb = __float2bfloat16(v[q]);
                h[q] = __bfloat162float(hb); l[q] = v[q]-h[q];
            }
            *(uint2*)(Chi + (size_t)row*ldc + bn + tx*4)      = make_uint2(packbf(h[0],h[1]), packbf(h[2],h[3]));
            *(uint2*)(Chi + (size_t)row*ldc + bn + 64 + tx*4) = make_uint2(packbf(h[4],h[5]), packbf(h[6],h[7]));
            *(uint2*)(Clo + (size_t)row*ldc + bn + tx*4)      = make_uint2(packbf(l[0],l[1]), packbf(l[2],l[3]));
            *(uint2*)(Clo + (size_t)row*ldc + bn + 64 + tx*4) = make_uint2(packbf(l[4],l[5]), packbf(l[6],l[7]));
        }
    }
}

// ---------------- HMMA bf16 split GEMM (R8 MMA body + cp.async staging) ------
// TERMS=3: (Ahi+Alo)@(Bhi+Blo)^T; TERMS=1: Ahi@Bhi^T only.
// OMODE: 0 = fp32 out, 1 = bf16 hi/lo split out, 2 = bf16 hi only.
__device__ __forceinline__ void mma16816(float* c, const unsigned* a, unsigned b0, unsigned b1){
    asm volatile(
        "mma.sync.aligned.m16n8k16.row.col.f32.bf16.bf16.f32 "
        "{%0,%1,%2,%3}, {%4,%5,%6,%7}, {%8,%9}, {%0,%1,%2,%3};"
        : "+f"(c[0]), "+f"(c[1]), "+f"(c[2]), "+f"(c[3])
        : "r"(a[0]), "r"(a[1]), "r"(a[2]), "r"(a[3]), "r"(b0), "r"(b1));
}

template<bool RELU, bool RB, int OMODE, int TERMS>
__global__ __launch_bounds__(256,2) void hgemm(
    const __nv_bfloat16* __restrict__ Ahi, const __nv_bfloat16* __restrict__ Alo,
    const __nv_bfloat16* __restrict__ Bhi, const __nv_bfloat16* __restrict__ Blo,
    const float* __restrict__ bias, const float* __restrict__ rowbias,
    __nv_bfloat16* __restrict__ Chi, __nv_bfloat16* __restrict__ Clo,
    float* __restrict__ Cf, int ldc, int K)
{
    __shared__ __nv_bfloat16 As[2][128][40];
    __shared__ __nv_bfloat16 Bs[2][128][40];
    const int tid  = threadIdx.x;
    const int wid  = tid >> 5, lane = tid & 31;
    const int g    = lane >> 2, tg = lane & 3;
    const int bm   = blockIdx.y * 128, bn = blockIdx.x * 128;
    const int wm   = (wid & 3) * 32, wn = (wid >> 2) * 64;
    const int rowA = tid >> 2;
    const int kq   = (tid & 3) * 8;

    const int nk  = K >> 5;
    const int nch = TERMS * nk;

    // cp.async destination addresses (per buffer)
    uint32_t dA0[2], dA1[2], dB0[2], dB1[2];
    #pragma unroll
    for (int b=0;b<2;b++){
        dA0[b] = (uint32_t)__cvta_generic_to_shared(&As[b][rowA][kq]);
        dA1[b] = (uint32_t)__cvta_generic_to_shared(&As[b][rowA+64][kq]);
        dB0[b] = (uint32_t)__cvta_generic_to_shared(&Bs[b][rowA][kq]);
        dB1[b] = (uint32_t)__cvta_generic_to_shared(&Bs[b][rowA+64][kq]);
    }

    float acc[2][8][4];
    #pragma unroll
    for (int mi=0;mi<2;mi++)
        #pragma unroll
        for (int ni=0;ni<8;ni++)
            #pragma unroll
            for (int q=0;q<4;q++) acc[mi][ni][q] = 0.f;

    auto issue = [&](int c, int buf){
        int term = c / nk, kc = c - term*nk;
        const __nv_bfloat16* Ab = (term<2) ? Ahi : Alo;
        const __nv_bfloat16* Bb = (term==1) ? Blo : Bhi;
        const __nv_bfloat16* ap = Ab + (size_t)(bm+rowA)*K + kc*32 + kq;
        const __nv_bfloat16* bp = Bb + (size_t)(bn+rowA)*K + kc*32 + kq;
        cp16(dA0[buf], ap);
        cp16(dA1[buf], ap + (size_t)64*K);
        cp16(dB0[buf], bp);
        cp16(dB1[buf], bp + (size_t)64*K);
        CP_COMMIT();
    };

    issue(0, 0);
    CP_WAIT0();
    __syncthreads();

    for (int c=0; c<nch; c++){
        const int buf = c & 1;
        const bool has = (c+1 < nch);
        if (has) issue(c+1, buf ^ 1);
        #pragma unroll
        for (int kk=0; kk<32; kk+=16){
            unsigned af[2][4];
            #pragma unroll
            for (int mi=0;mi<2;mi++){
                const int rb0 = wm + mi*16 + g;
                af[mi][0] = *(const unsigned*)&As[buf][rb0  ][kk + tg*2];
                af[mi][1] = *(const unsigned*)&As[buf][rb0+8][kk + tg*2];
                af[mi][2] = *(const unsigned*)&As[buf][rb0  ][kk + 8 + tg*2];
                af[mi][3] = *(const unsigned*)&As[buf][rb0+8][kk + 8 + tg*2];
            }
            #pragma unroll
            for (int ni=0;ni<8;ni++){
                const int nr = wn + ni*8 + g;
                unsigned bw0 = *(const unsigned*)&Bs[buf][nr][kk + tg*2];
                unsigned bw1 = *(const unsigned*)&Bs[buf][nr][kk + 8 + tg*2];
                mma16816(acc[0][ni], af[0], bw0, bw1);
                mma16816(acc[1][ni], af[1], bw0, bw1);
            }
        }
        if (has) CP_WAIT0();
        __syncthreads();
    }

    // epilogue
    #pragma unroll
    for (int mi=0;mi<2;mi++){
        const int ra = bm + wm + mi*16 + g;
        const int rb_ = ra + 8;
        #pragma unroll
        for (int ni=0;ni<8;ni++){
            const int col = bn + wn + ni*8 + tg*2;
            float2 bv = *(const float2*)&bias[col];
            float v00 = acc[mi][ni][0] + bv.x, v01 = acc[mi][ni][1] + bv.y;
            float v10 = acc[mi][ni][2] + bv.x, v11 = acc[mi][ni][3] + bv.y;
            if (RB){
                float2 r0 = *(const float2*)&rowbias[(size_t)ra*ldc + col];
                float2 r1 = *(const float2*)&rowbias[(size_t)rb_*ldc + col];
                v00+=r0.x; v01+=r0.y; v10+=r1.x; v11+=r1.y;
            }
            if (RELU){
                v00=fmaxf(v00,0.f); v01=fmaxf(v01,0.f);
                v10=fmaxf(v10,0.f); v11=fmaxf(v11,0.f);
            }
            if (OMODE == 0){
                *(float2*)&Cf[(size_t)ra*ldc + col]  = make_float2(v00,v01);
                *(float2*)&Cf[(size_t)rb_*ldc + col] = make_float2(v10,v11);
            } else if (OMODE == 2){
                *(unsigned*)&Chi[(size_t)ra*ldc + col]  = packbf(v00,v01);
                *(unsigned*)&Chi[(size_t)rb_*ldc + col] = packbf(v10,v11);
            } else {
                float h00=__bfloat162float(__float2bfloat16(v00));
                float h01=__bfloat162float(__float2bfloat16(v01));
                float h10=__bfloat162float(__float2bfloat16(v10));
                float h11=__bfloat162float(__float2bfloat16(v11));
                *(unsigned*)&Chi[(size_t)ra*ldc + col]  = packbf(h00,h01);
                *(unsigned*)&Chi[(size_t)rb_*ldc + col] = packbf(h10,h11);
                *(unsigned*)&Clo[(size_t)ra*ldc + col]  = packbf(v00-h00, v01-h01);
                *(unsigned*)&Clo[(size_t)rb_*ldc + col] = packbf(v10-h10, v11-h11);
            }
        }
    }
}

// ---------------- LayerNorm over rows of 256 ---------------------------------
template<bool SPLIT>
__global__ void ln_kernel(const float* __restrict__ z, const float* __restrict__ gg,
                          const float* __restrict__ bb,
                          __nv_bfloat16* __restrict__ oh, __nv_bfloat16* __restrict__ ol,
                          float* __restrict__ of)
{
    int row  = blockIdx.x*8 + (threadIdx.x>>5);
    int lane = threadIdx.x & 31;
    const float* rr = z + (size_t)row*256 + lane*8;
    float v[8];
    float4 p0 = *(const float4*)rr;
    float4 p1 = *(const float4*)(rr+4);
    v[0]=p0.x;v[1]=p0.y;v[2]=p0.z;v[3]=p0.w;v[4]=p1.x;v[5]=p1.y;v[6]=p1.z;v[7]=p1.w;
    float s=0.f;
    #pragma unroll
    for (int j=0;j<8;j++) s+=v[j];
    #pragma unroll
    for (int off=16;off>0;off>>=1) s += __shfl_xor_sync(0xffffffffu, s, off);
    float mu = s * (1.f/256.f);
    float q=0.f;
    #pragma unroll
    for (int j=0;j<8;j++){ float d=v[j]-mu; q+=d*d; }
    #pragma unroll
    for (int off=16;off>0;off>>=1) q += __shfl_xor_sync(0xffffffffu, q, off);
    float inv = rsqrtf(q*(1.f/256.f) + 1e-5f);
    size_t off = (size_t)row*256 + lane*8;
    if (SPLIT){
        float h[8], l[8];
        #pragma unroll
        for (int j=0;j<8;j++){
            float o = (v[j]-mu)*inv*gg[lane*8+j] + bb[lane*8+j];
            __nv_bfloat16 hb = __float2bfloat16(o);
            h[j] = __bfloat162float(hb); l[j] = o - h[j];
        }
        *(uint4*)(oh+off) = make_uint4(packbf(h[0],h[1]),packbf(h[2],h[3]),packbf(h[4],h[5]),packbf(h[6],h[7]));
        *(uint4*)(ol+off) = make_uint4(packbf(l[0],l[1]),packbf(l[2],l[3]),packbf(l[4],l[5]),packbf(l[6],l[7]));
    } else {
        #pragma unroll
        for (int j=0;j<8;j++)
            of[off+j] = (v[j]-mu)*inv*gg[lane*8+j] + bb[lane*8+j];
    }
}

// ---------------- importance scalar ------------------------------------------
__global__ void imp_kernel(const float* __restrict__ z, const float* __restrict__ iw3,
                           const float* __restrict__ ib3, float* __restrict__ imp)
{
    int row  = blockIdx.x*8 + (threadIdx.x>>5);
    int lane = threadIdx.x & 31;
    const float* r = z + (size_t)row*256 + lane*8;
    float s = 0.f;
    #pragma unroll
    for (int j=0;j<8;j++) s += r[j]*iw3[lane*8+j];
    #pragma unroll
    for (int off=16;off>0;off>>=1) s += __shfl_xor_sync(0xffffffffu, s, off);
    if (lane==0) imp[row] = s + ib3[0];
}

// ---------------- per-batch top-256 candidates (approx keys) ------------------
__global__ void topk256_kernel(const float* __restrict__ imp, const float* __restrict__ noise,
                               int* __restrict__ cand)
{
    extern __shared__ unsigned skey[];
    __shared__ unsigned hist[256];
    __shared__ unsigned s_prefix, s_mask;
    __shared__ int s_rem, s_cnt, s_eqcnt;
    __shared__ int eqbuf[512];
    const int b = blockIdx.x;
    const int tid = threadIdx.x;
    for (int i=tid;i<PB;i+=1024)
        skey[i] = f2u(imp[b*PB+i] + noise[b*PB+i]);
    if (tid==0){ s_prefix=0u; s_mask=0u; s_rem=KSEL; }
    __syncthreads();
    for (int round=0; round<4; round++){
        const int shift = 24 - 8*round;
        if (tid<256) hist[tid]=0u;
        __syncthreads();
        unsigned mask = s_mask, prefix = s_prefix;
        for (int i=tid;i<PB;i+=1024){
            unsigned k = skey[i];
            if ((k & mask) == prefix) atomicAdd(&hist[(k>>shift)&255u], 1u);
        }
        __syncthreads();
        if (tid==0){
            int rem = s_rem; unsigned cum=0; int bsel=0;
            for (int bin=255; bin>=0; bin--){
                if (cum + hist[bin] >= (unsigned)rem){ bsel=bin; break; }
                cum += hist[bin];
            }
            s_rem    = rem - (int)cum;
            s_prefix = prefix | ((unsigned)bsel << shift);
            s_mask   = mask   | (0xFFu << shift);
        }
        __syncthreads();
    }
    const unsigned kth = s_prefix;
    const int rEq = s_rem;
    if (tid==0){ s_cnt=0; s_eqcnt=0; }
    __syncthreads();
    for (int i=tid;i<PB;i+=1024){
        unsigned k = skey[i];
        if (k > kth){
            int p = atomicAdd(&s_cnt,1);
            cand[b*KSEL+p] = i;
        } else if (k == kth){
            int p = atomicAdd(&s_eqcnt,1);
            if (p < 512) eqbuf[p] = i;
        }
    }
    __syncthreads();
    if (tid==0){
        int base = s_cnt;
        for (int a=0;a<rEq;a++) cand[b*KSEL+base+a] = eqbuf[a];
    }
}

// ---------------- gather candidate inputs -------------------------------------
__global__ void cand_gather(const int* __restrict__ cand,
                            float* __restrict__ xc, float* __restrict__ rbc)
{
    const int j = blockIdx.x;
    const int b = j >> 8;
    const int i = cand[j];
    const int gidx = b*PB + i;
    const int t = threadIdx.x;
    if (t < 2) ((float4*)xc)[j*2+t] = ((const float4*)g_x8)[(size_t)gidx*2+t];
    ((float4*)rbc)[(size_t)j*64+t] = ((const float4*)g_rb)[(size_t)gidx*64+t];
}

// ---------------- exact top-128 among candidates ------------------------------
__global__ void topk_final(const float* __restrict__ impc, const float* __restrict__ noise,
                           const int* __restrict__ cand, const float* __restrict__ c4,
                           float* __restrict__ cent)
{
    __shared__ unsigned long long s[KSEL];
    const int b = blockIdx.x, t = threadIdx.x;
    const int i = cand[b*KSEL+t];
    float v = impc[b*KSEL+t] + noise[b*PB+i];
    s[t] = ((unsigned long long)(~f2u(v)) << 32) | (unsigned)i;
    __syncthreads();
    for (int ksz=2; ksz<=KSEL; ksz<<=1){
        for (int j=ksz>>1; j>0; j>>=1){
            int ixj = t ^ j;
            if (ixj > t){
                unsigned long long a = s[t], c = s[ixj];
                bool up = ((t & ksz) == 0);
                if (up ? (a > c) : (a < c)){ s[t]=c; s[ixj]=a; }
            }
            __syncthreads();
        }
    }
    if (t < MTOK){
        int i2 = (unsigned)(s[t] & 0xffffffffu);
        #pragma unroll
        for (int q=0;q<4;q++) cent[(b*MTOK+t)*4+q] = c4[(size_t)(b*PB+i2)*4+q];
    }
}

// ---------------- stable sort of 128 cents by t -------------------------------
__global__ void sortt_kernel(const float* __restrict__ cent, int* __restrict__ order)
{
    __shared__ unsigned long long s[128];
    const int b = blockIdx.x, tid = threadIdx.x;
    float t = cent[(b*MTOK+tid)*4+3];
    s[tid] = ((unsigned long long)f2u(t) << 32) | (unsigned)tid;
    __syncthreads();
    for (int ksz=2; ksz<=128; ksz<<=1){
        for (int j=ksz>>1; j>0; j>>=1){
            int ixj = tid ^ j;
            if (ixj > tid){
                unsigned long long a = s[tid], c = s[ixj];
                bool up = ((tid & ksz) == 0);
                if (up ? (a > c) : (a < c)){ s[tid]=c; s[ixj]=a; }
            }
            __syncthreads();
        }
    }
    order[b*MTOK+tid] = (int)(s[tid] & 0xffffffffu);
}

// ---------------- brute-force 16-NN -------------------------------------------
__global__ void knn_kernel(const float* __restrict__ c4, const float* __restrict__ cent,
                           int* __restrict__ knn)
{
    __shared__ unsigned long long lists[128][KNN];
    const int bm = blockIdx.x;
    const int b  = bm >> 7;
    const int tid = threadIdx.x;
    const float cx = cent[bm*4+0], cy = cent[bm*4+1], cz = cent[bm*4+2], ct = cent[bm*4+3];
    unsigned long long loc[KNN];
    #pragma unroll
    for (int q=0;q<KNN;q++) loc[q] = ~0ull;
    const float* cb = c4 + (size_t)b*PB*4;
    for (int i=tid;i<PB;i+=128){
        float4 p = *(const float4*)(cb + (size_t)i*4);
        float dx=p.x-cx, dy=p.y-cy, dz=p.z-cz, dt=p.w-ct;
        float d2 = dx*dx + dy*dy + dz*dz + dt*dt;
        unsigned long long key = ((unsigned long long)(__float_as_uint(d2)|0x80000000u) << 32) | (unsigned)i;
        if (key < loc[KNN-1]){
            loc[KNN-1] = key;
            #pragma unroll
            for (int q=KNN-1;q>0;q--){
                if (loc[q] < loc[q-1]){ unsigned long long t=loc[q]; loc[q]=loc[q-1]; loc[q-1]=t; }
            }
        }
    }
    #pragma unroll
    for (int q=0;q<KNN;q++) lists[tid][q]=loc[q];
    __syncthreads();
    for (int sgap=64; sgap>0; sgap>>=1){
        if (tid < sgap){
            unsigned long long out[KNN];
            int i1=0, i2=0;
            #pragma unroll
            for (int q=0;q<KNN;q++){
                unsigned long long a=lists[tid][i1], c=lists[tid+sgap][i2];
                if (a<=c){ out[q]=a; i1++; } else { out[q]=c; i2++; }
            }
            #pragma unroll
            for (int q=0;q<KNN;q++) lists[tid][q]=out[q];
        }
        __syncthreads();
    }
    if (tid < KNN) knn[bm*KNN+tid] = (int)(lists[0][tid] & 0xffffffffu);
}

// ---------------- gather x8 rows of knn neighbors -----------------------------
__global__ void gatherx_kernel(const int* __restrict__ knn, float* __restrict__ gx)
{
    const int r = blockIdx.x*256 + threadIdx.x;   // 0..NGATH-1
    const int bm = r / KNN;
    const int b  = bm >> 7;
    const int nb = b*PB + knn[r];
    ((float4*)gx)[(size_t)r*2+0] = ((const float4*)g_x8)[(size_t)nb*2+0];
    ((float4*)gx)[(size_t)r*2+1] = ((const float4*)g_x8)[(size_t)nb*2+1];
}

// ---------------- max pool over groups of 16 ----------------------------------
__global__ void pool_kernel(const float* __restrict__ pfg, float* __restrict__ pooled)
{
    const int bm = blockIdx.x;
    const int tid = threadIdx.x;
    for (int c=tid;c<TOKD;c+=256){
        float m = -3.402823466e38f;
        #pragma unroll
        for (int q=0;q<KNN;q++)
            m = fmaxf(m, pfg[(size_t)(bm*KNN+q)*768 + c]);
        pooled[(size_t)bm*TOKD + c] = m;
    }
}

// ---------------- scatter to output in time order -----------------------------
__global__ void out_kernel(const float* __restrict__ tok, const float* __restrict__ cent,
                           const int* __restrict__ order, float* __restrict__ out)
{
    const int bj = blockIdx.x;
    const int b  = bj >> 7;
    const int o  = order[bj];
    const float* src = tok + (size_t)(b*MTOK+o)*TOKD;
    float* dst = out + (size_t)bj*TOKD;
    for (int c=threadIdx.x;c<TOKD;c+=256) dst[c]=src[c];
    if (threadIdx.x < 4) out[(size_t)BATCH*MTOK*TOKD + bj*4 + threadIdx.x] = cent[(b*MTOK+o)*4+threadIdx.x];
    if (threadIdx.x == 4) out[(size_t)BATCH*MTOK*TOKD + (size_t)BATCH*MTOK*4 + bj] = 1.0f;
}

// ---------------- launch ------------------------------------------------------
extern "C" void kernel_launch(void* const* d_in, const int* in_sizes, int n_in,
                              void* d_out, int out_size)
{
    (void)in_sizes; (void)n_in; (void)out_size;
    const float* coords = (const float*)d_in[0];
    const float* feats  = (const float*)d_in[1];
    const float* w1  = (const float*)d_in[3];  const float* b1  = (const float*)d_in[4];
    const float* w2  = (const float*)d_in[5];  const float* b2  = (const float*)d_in[6];
    const float* w3  = (const float*)d_in[7];  const float* b3  = (const float*)d_in[8];
    const float* w4  = (const float*)d_in[9];  const float* b4  = (const float*)d_in[10];
    const float* iw1 = (const float*)d_in[11]; const float* ib1 = (const float*)d_in[12];
    const float* lng = (const float*)d_in[13]; const float* lnb = (const float*)d_in[14];
    const float* iw2 = (const float*)d_in[15]; const float* ib2 = (const float*)d_in[16];
    const float* iw3 = (const float*)d_in[17]; const float* ib3 = (const float*)d_in[18];
    const float* nw1 = (const float*)d_in[19]; const float* nb1 = (const float*)d_in[20];
    const float* nw2 = (const float*)d_in[21]; const float* nb2 = (const float*)d_in[22];
    const float* noise = (const float*)d_in[23];

    void *px8,*pw1p,*pc4,*ph1h,*ph1l,*ph2h,*ph3h,*pwp,*pbp,*pz0,*prb;
    void *pz1,*pz2h,*pz2l,*pz3,*pimp,*pcand,*pxc,*prbc,*ph1c,*ph2c,*ph3c,*pz1c,*pz2c,*pz3c,*pimpc;
    void *pcent,*pord,*pknn,*pgx,*ph1gh,*ph1gl,*ph2gh,*ph2gl,*pgh,*pgl,*ppfg,*ppool,*pt1,*ptok;
    void *pw2h,*pw2l,*pw3h,*pw3l,*pw4h,*pw4l,*pwph,*pwpl,*piw2h,*piw2l;
    cudaGetSymbolAddress(&px8,g_x8);     cudaGetSymbolAddress(&pw1p,g_w1p);
    cudaGetSymbolAddress(&pc4,g_c4);
    cudaGetSymbolAddress(&ph1h,g_h1h);   cudaGetSymbolAddress(&ph1l,g_h1l);
    cudaGetSymbolAddress(&ph2h,g_h2h);   cudaGetSymbolAddress(&ph3h,g_h3h);
    cudaGetSymbolAddress(&pwp,g_wp);     cudaGetSymbolAddress(&pbp,g_biasp);
    cudaGetSymbolAddress(&pz0,g_zero256);cudaGetSymbolAddress(&prb,g_rb);
    cudaGetSymbolAddress(&pz1,g_z1);     cudaGetSymbolAddress(&pz2h,g_z2h);
    cudaGetSymbolAddress(&pz2l,g_z2l);   cudaGetSymbolAddress(&pz3,g_z3);
    cudaGetSymbolAddress(&pimp,g_imp);   cudaGetSymbolAddress(&pcand,g_cand);
    cudaGetSymbolAddress(&pxc,g_xc);     cudaGetSymbolAddress(&prbc,g_rbc);
    cudaGetSymbolAddress(&ph1c,g_h1c);   cudaGetSymbolAddress(&ph2c,g_h2c);
    cudaGetSymbolAddress(&ph3c,g_h3c);   cudaGetSymbolAddress(&pz1c,g_z1c);
    cudaGetSymbolAddress(&pz2c,g_z2c);   cudaGetSymbolAddress(&pz3c,g_z3c);
    cudaGetSymbolAddress(&pimpc,g_impc);
    cudaGetSymbolAddress(&pcent,g_cent); cudaGetSymbolAddress(&pord,g_order);
    cudaGetSymbolAddress(&pknn,g_knn);   cudaGetSymbolAddress(&pgx,g_gx);
    cudaGetSymbolAddress(&ph1gh,g_h1gh); cudaGetSymbolAddress(&ph1gl,g_h1gl);
    cudaGetSymbolAddress(&ph2gh,g_h2gh); cudaGetSymbolAddress(&ph2gl,g_h2gl);
    cudaGetSymbolAddress(&pgh,g_gh);     cudaGetSymbolAddress(&pgl,g_gl);
    cudaGetSymbolAddress(&ppfg,g_pfg);   cudaGetSymbolAddress(&ppool,g_pooled);
    cudaGetSymbolAddress(&pt1,g_t1);     cudaGetSymbolAddress(&ptok,g_tok);
    cudaGetSymbolAddress(&pw2h,g_w2th);  cudaGetSymbolAddress(&pw2l,g_w2tl);
    cudaGetSymbolAddress(&pw3h,g_w3th);  cudaGetSymbolAddress(&pw3l,g_w3tl);
    cudaGetSymbolAddress(&pw4h,g_w4th);  cudaGetSymbolAddress(&pw4l,g_w4tl);
    cudaGetSymbolAddress(&pwph,g_wpth);  cudaGetSymbolAddress(&pwpl,g_wptl);
    cudaGetSymbolAddress(&piw2h,g_iw2th);cudaGetSymbolAddress(&piw2l,g_iw2tl);

    cudaFuncSetAttribute(topk256_kernel, cudaFuncAttributeMaxDynamicSharedMemorySize, PB*4);

    prep_points<<<NPTS/256, 256>>>(coords, feats);
    prep_w<<<8, 256>>>(w1);
    biasp_init<<<1,256>>>(ib1, (float*)pbp);
    biasp_acc<<<8,256>>>(b4, iw1, (float*)pbp);
    rb_kernel<<<NPTS/4,256>>>((const float*)pc4, iw1, (float*)prb);
    sgemm128<false,false,0><<<dim3(2,6),256>>>(w4, 768, iw1, 256, (const float*)pz0,
        nullptr, (float*)pwp, nullptr, nullptr, 256, 768);
    conv_wt<<<(512*256+255)/256,256>>>(w2, 256, 512, (__nv_bfloat16*)pw2h, (__nv_bfloat16*)pw2l);
    conv_wt<<<(768*512+255)/256,256>>>(w3, 512, 768, (__nv_bfloat16*)pw3h, (__nv_bfloat16*)pw3l);
    conv_wt<<<(768*768+255)/256,256>>>(w4, 768, 768, (__nv_bfloat16*)pw4h, (__nv_bfloat16*)pw4l);
    conv_wt<<<(256*768+255)/256,256>>>((const float*)pwp, 768, 256, (__nv_bfloat16*)pwph, (__nv_bfloat16*)pwpl);
    conv_wt<<<(256*256+255)/256,256>>>(iw2, 256, 256, (__nv_bfloat16*)piw2h, (__nv_bfloat16*)piw2l);

    // L1 scalar -> h1 split (full points)
    sgemm128<true,false,1><<<dim3(2,1024),256>>>((const float*)px8, 8, (const float*)pw1p, 256, b1,
        nullptr, nullptr, (__nv_bfloat16*)ph1h, (__nv_bfloat16*)ph1l, 256, 8);
    // trunk 1-term (importance-only precision), bf16-hi outputs
    hgemm<true,false,2,1><<<dim3(4,1024),256>>>((const __nv_bfloat16*)ph1h,(const __nv_bfloat16*)ph1l,
        (const __nv_bfloat16*)pw2h,(const __nv_bfloat16*)pw2l, b2, nullptr,
        (__nv_bfloat16*)ph2h, nullptr, nullptr, 512, 256);
    hgemm<true,false,2,1><<<dim3(6,1024),256>>>((const __nv_bfloat16*)ph2h, nullptr,
        (const __nv_bfloat16*)pw3h,(const __nv_bfloat16*)pw3l, b3, nullptr,
        (__nv_bfloat16*)ph3h, nullptr, nullptr, 768, 512);
    // importance branch (1-term)
    hgemm<true,true,0,1><<<dim3(2,1024),256>>>((const __nv_bfloat16*)ph3h, nullptr,
        (const __nv_bfloat16*)pwph,(const __nv_bfloat16*)pwpl, (const float*)pbp, (const float*)prb,
        nullptr, nullptr, (float*)pz1, 256, 768);
    ln_kernel<true><<<NPTS/8,256>>>((const float*)pz1, lng, lnb,
        (__nv_bfloat16*)pz2h, (__nv_bfloat16*)pz2l, nullptr);
    hgemm<true,false,0,1><<<dim3(2,1024),256>>>((const __nv_bfloat16*)pz2h,(const __nv_bfloat16*)pz2l,
        (const __nv_bfloat16*)piw2h,(const __nv_bfloat16*)piw2l, ib2, nullptr,
        nullptr, nullptr, (float*)pz3, 256, 256);
    imp_kernel<<<NPTS/8,256>>>((const float*)pz3, iw3, ib3, (float*)pimp);

    // approx top-256 candidates, then exact scalar refinement
    topk256_kernel<<<BATCH,1024,PB*4>>>((const float*)pimp, noise, (int*)pcand);
    cand_gather<<<NCAND,64>>>((const int*)pcand, (float*)pxc, (float*)prbc);
    sgemm128<true,false,0><<<dim3(2,16),256>>>((const float*)pxc, 8, (const float*)pw1p, 256, b1,
        nullptr, (float*)ph1c, nullptr, nullptr, 256, 8);
    sgemm128<true,false,0><<<dim3(4,16),256>>>((const float*)ph1c, 256, w2, 512, b2,
        nullptr, (float*)ph2c, nullptr, nullptr, 512, 256);
    sgemm128<true,false,0><<<dim3(6,16),256>>>((const float*)ph2c, 512, w3, 768, b3,
        nullptr, (float*)ph3c, nullptr, nullptr, 768, 512);
    sgemm128<true,true,0><<<dim3(2,16),256>>>((const float*)ph3c, 768, (const float*)pwp, 256,
        (const float*)pbp, (const float*)prbc, (float*)pz1c, nullptr, nullptr, 256, 768);
    ln_kernel<false><<<NCAND/8,256>>>((const float*)pz1c, lng, lnb, nullptr, nullptr, (float*)pz2c);
    sgemm128<true,false,0><<<dim3(2,16),256>>>((const float*)pz2c, 256, iw2, 256, ib2,
        nullptr, (float*)pz3c, nullptr, nullptr, 256, 256);
    imp_kernel<<<NCAND/8,256>>>((const float*)pz3c, iw3, ib3, (float*)pimpc);
    topk_final<<<BATCH,KSEL>>>((const float*)pimpc, noise, (const int*)pcand,
                               (const float*)pc4, (float*)pcent);

    // neighborhoods (coordinates only)
    sortt_kernel<<<BATCH,128>>>((const float*)pcent, (int*)pord);
    knn_kernel<<<BATCH*MTOK,128>>>((const float*)pc4, (const float*)pcent, (int*)pknn);

    // neighbor trunk recompute at full (3-term) precision: 16384 rows
    gatherx_kernel<<<NGATH/256,256>>>((const int*)pknn, (float*)pgx);
    sgemm128<true,false,1><<<dim3(2,NGATH/128),256>>>((const float*)pgx, 8, (const float*)pw1p, 256, b1,
        nullptr, nullptr, (__nv_bfloat16*)ph1gh, (__nv_bfloat16*)ph1gl, 256, 8);
    hgemm<true,false,1,3><<<dim3(4,NGATH/128),256>>>((const __nv_bfloat16*)ph1gh,(const __nv_bfloat16*)ph1gl,
        (const __nv_bfloat16*)pw2h,(const __nv_bfloat16*)pw2l, b2, nullptr,
        (__nv_bfloat16*)ph2gh,(__nv_bfloat16*)ph2gl, nullptr, 512, 256);
    hgemm<true,false,1,3><<<dim3(6,NGATH/128),256>>>((const __nv_bfloat16*)ph2gh,(const __nv_bfloat16*)ph2gl,
        (const __nv_bfloat16*)pw3h,(const __nv_bfloat16*)pw3l, b3, nullptr,
        (__nv_bfloat16*)pgh,(__nv_bfloat16*)pgl, nullptr, 768, 512);
    hgemm<false,false,0,3><<<dim3(6,NGATH/128),256>>>((const __nv_bfloat16*)pgh,(const __nv_bfloat16*)pgl,
        (const __nv_bfloat16*)pw4h,(const __nv_bfloat16*)pw4l, b4, nullptr,
        nullptr, nullptr, (float*)ppfg, 768, 768);
    pool_kernel<<<BATCH*MTOK,256>>>((const float*)ppfg, (float*)ppool);

    // token MLP scalar fp32
    sgemm128<true ,false,0><<<dim3(6,8),256>>>((const float*)ppool, 768, nw1, 768, nb1,
        nullptr, (float*)pt1, nullptr, nullptr, 768, 768);
    sgemm128<false,false,0><<<dim3(6,8),256>>>((const float*)pt1, 768, nw2, 768, nb2,
        nullptr, (float*)ptok, nullptr, nullptr, 768, 768);

    out_kernel<<<BATCH*MTOK,256>>>((const float*)ptok, (const float*)pcent, (const int*)pord, (float*)d_out);
}

// round 14
// speedup vs baseline: 1.0397x; 1.0397x over previous
#include <cuda_runtime.h>
#include <cuda_bf16.h>
#include <math.h>
#include <stdint.h>

#define NPTS   131072
#define PB     16384
#define BATCH  8
#define MTOK   128
#define KNN    16
#define TOKD   768
#define NGATH  (BATCH*MTOK*KNN)   // 16384 gathered neighbor rows
#define KSEL   256                // candidate pool per batch
#define NCAND  (BATCH*KSEL)       // 2048

// ---------------- scratch (device globals; no allocs allowed) ----------------
__device__ __align__(16) float g_x8[NPTS*8];
__device__ __align__(16) float g_w1p[8*256];
__device__ __align__(16) float g_c4[NPTS*4];
__device__ __align__(16) __nv_bfloat16 g_h1h[(size_t)NPTS*256];
__device__ __align__(16) __nv_bfloat16 g_h2h[(size_t)NPTS*512];
__device__ __align__(16) __nv_bfloat16 g_h3h[(size_t)NPTS*768];
__device__ __align__(16) float g_wp[768*256];          // w4 @ iw1[0:768]
__device__ __align__(16) float g_biasp[256];
__device__ __align__(16) float g_zero256[256];         // stays zero
__device__ __align__(16) float g_z1[(size_t)NPTS*256];
__device__ __align__(16) __nv_bfloat16 g_z2h[(size_t)NPTS*256];
__device__ __align__(16) float g_z3[(size_t)NPTS*256];
__device__ float g_imp[NPTS];
// split weights [N][K] bf16 hi/lo
__device__ __align__(16) __nv_bfloat16 g_w2th[512*256],  g_w2tl[512*256];
__device__ __align__(16) __nv_bfloat16 g_w3th[768*512],  g_w3tl[768*512];
__device__ __align__(16) __nv_bfloat16 g_w4th[768*768],  g_w4tl[768*768];
__device__ __align__(16) __nv_bfloat16 g_wpth[256*768],  g_wptl[256*768];
__device__ __align__(16) __nv_bfloat16 g_iw2th[256*256], g_iw2tl[256*256];
// refinement
__device__ int   g_cand[NCAND];
__device__ __align__(16) float g_xc[NCAND*8];
__device__ __align__(16) float g_rbc[NCAND*256];
__device__ __align__(16) float g_h1c[NCAND*256];
__device__ __align__(16) float g_h2c[NCAND*512];
__device__ __align__(16) float g_h3c[NCAND*768];
__device__ __align__(16) float g_z1c[NCAND*256];
__device__ __align__(16) float g_z2c[NCAND*256];
__device__ __align__(16) float g_z3c[NCAND*256];
__device__ float g_impc[NCAND];
// selection + neighbor recompute
__device__ float g_cent[BATCH*MTOK*4];
__device__ int   g_order[BATCH*MTOK];
__device__ int   g_knn[BATCH*MTOK*KNN];
__device__ __align__(16) float g_gx[NGATH*8];
__device__ __align__(16) __nv_bfloat16 g_h1gh[(size_t)NGATH*256], g_h1gl[(size_t)NGATH*256];
__device__ __align__(16) __nv_bfloat16 g_h2gh[(size_t)NGATH*512], g_h2gl[(size_t)NGATH*512];
__device__ __align__(16) __nv_bfloat16 g_gh[(size_t)NGATH*768], g_gl[(size_t)NGATH*768];
__device__ __align__(16) float g_pfg[(size_t)NGATH*768];
__device__ __align__(16) float g_pooled[BATCH*MTOK*TOKD];
__device__ __align__(16) float g_t1[BATCH*MTOK*TOKD];
__device__ __align__(16) float g_tok[BATCH*MTOK*TOKD];

__device__ __forceinline__ unsigned packbf(float lo, float hi){
    unsigned r; asm("cvt.rn.bf16x2.f32 %0, %2, %1;" : "=r"(r) : "f"(lo), "f"(hi)); return r;
}
__device__ __forceinline__ unsigned f2u(float x){
    unsigned u = __float_as_uint(x);
    return (u & 0x80000000u) ? ~u : (u | 0x80000000u);
}

// ---------------- prep -------------------------------------------------------
__global__ void prep_points(const float* __restrict__ coords,
                            const float* __restrict__ feats)
{
    int i = blockIdx.x*blockDim.x + threadIdx.x;
    if (i >= NPTS) return;
    #pragma unroll
    for (int j=0;j<6;j++) g_x8[i*8+j] = feats[i*6+j];
    g_x8[i*8+6]=0.f; g_x8[i*8+7]=0.f;
    #pragma unroll
    for (int j=0;j<4;j++) g_c4[i*4+j] = coords[i*5+1+j];
}
__global__ void prep_w(const float* __restrict__ w1)
{
    int idx = blockIdx.x*blockDim.x + threadIdx.x;
    if (idx < 8*256) g_w1p[idx] = (idx < 6*256) ? w1[idx] : 0.f;
}
__global__ void biasp_init(const float* __restrict__ ib1, float* __restrict__ bp)
{ bp[threadIdx.x] = ib1[threadIdx.x]; }
__global__ void biasp_acc(const float* __restrict__ b4, const float* __restrict__ iw1,
                          float* __restrict__ bp)
{
    int n = threadIdx.x;
    int j0 = blockIdx.x*96;
    float s = 0.f;
    for (int j=j0;j<j0+96;j++) s += b4[j]*iw1[(size_t)j*256+n];
    atomicAdd(&bp[n], s);
}
__global__ void conv_wt(const float* __restrict__ src, int K, int N,
                        __nv_bfloat16* __restrict__ dh, __nv_bfloat16* __restrict__ dl)
{
    int idx = blockIdx.x*blockDim.x + threadIdx.x;
    if (idx >= N*K) return;
    int n = idx / K, k = idx - n*K;
    float v = src[(size_t)k*N + n];
    __nv_bfloat16 h = __float2bfloat16(v);
    dh[idx] = h;
    dl[idx] = __float2bfloat16(v - __bfloat162float(h));
}

// ---------------- scalar SGEMM (proven core) ---------------------------------
// OM: 0 fp32 out, 1 bf16 hi/lo split out, 2 bf16 hi-only out
template<bool RELU, bool RB, int OM>
__global__ __launch_bounds__(256,2) void sgemm128(
    const float* __restrict__ A, int lda,
    const float* __restrict__ B, int N,
    const float* __restrict__ bias,
    const float* __restrict__ rowbias,
    float* __restrict__ C,
    __nv_bfloat16* __restrict__ Chi, __nv_bfloat16* __restrict__ Clo,
    int ldc, int K)
{
    __shared__ float As[2][8][128];
    __shared__ float Bs[2][8][128];
    const int tid  = threadIdx.x;
    const int bm   = blockIdx.y * 128;
    const int bn   = blockIdx.x * 128;
    const int arow = tid >> 1;
    const int acol = (tid & 1) * 4;
    const int brow = tid >> 5;
    const int bcol = (tid & 31) * 4;
    const int tx   = tid & 15;
    const int ty   = tid >> 4;

    const float* Aptr = A + (size_t)(bm + arow) * lda + acol;
    const float* Bptr = B + (size_t)brow * N + bn + bcol;

    float acc[8][8];
    #pragma unroll
    for (int i=0;i<8;i++)
        #pragma unroll
        for (int j=0;j<8;j++) acc[i][j]=0.f;

    {
        float4 a = *(const float4*)Aptr;
        As[0][acol+0][arow]=a.x; As[0][acol+1][arow]=a.y;
        As[0][acol+2][arow]=a.z; As[0][acol+3][arow]=a.w;
        *(float4*)&Bs[0][brow][bcol] = *(const float4*)Bptr;
    }
    __syncthreads();

    const int ktiles = K >> 3;
    int buf = 0;
    for (int kt=0; kt<ktiles; kt++){
        float4 a, bv;
        const bool has = (kt+1 < ktiles);
        if (has){
            a  = *(const float4*)(Aptr + (kt+1)*8);
            bv = *(const float4*)(Bptr + (size_t)(kt+1)*8*N);
        }
        #pragma unroll
        for (int k=0;k<8;k++){
            float4 a0 = *(const float4*)&As[buf][k][ty*4];
            float4 a1 = *(const float4*)&As[buf][k][64+ty*4];
            float4 b0 = *(const float4*)&Bs[buf][k][tx*4];
            float4 b1 = *(const float4*)&Bs[buf][k][64+tx*4];
            float ar[8] = {a0.x,a0.y,a0.z,a0.w,a1.x,a1.y,a1.z,a1.w};
            float br[8] = {b0.x,b0.y,b0.z,b0.w,b1.x,b1.y,b1.z,b1.w};
            #pragma unroll
            for (int i=0;i<8;i++)
                #pragma unroll
                for (int j=0;j<8;j++)
                    acc[i][j] += ar[i]*br[j];
        }
        if (has){
            const int nb = buf^1;
            As[nb][acol+0][arow]=a.x; As[nb][acol+1][arow]=a.y;
            As[nb][acol+2][arow]=a.z; As[nb][acol+3][arow]=a.w;
            *(float4*)&Bs[nb][brow][bcol] = bv;
        }
        __syncthreads();
        buf ^= 1;
    }

    float4 bv0 = *(const float4*)(bias + bn + tx*4);
    float4 bv1 = *(const float4*)(bias + bn + 64 + tx*4);
    #pragma unroll
    for (int i=0;i<8;i++){
        const int row = bm + ((i<4) ? (ty*4+i) : (64 + ty*4 + i - 4));
        float4 o0, o1;
        o0.x=acc[i][0]+bv0.x; o0.y=acc[i][1]+bv0.y; o0.z=acc[i][2]+bv0.z; o0.w=acc[i][3]+bv0.w;
        o1.x=acc[i][4]+bv1.x; o1.y=acc[i][5]+bv1.y; o1.z=acc[i][6]+bv1.z; o1.w=acc[i][7]+bv1.w;
        if (RB){
            float4 r0 = *(const float4*)(rowbias + (size_t)row*ldc + bn + tx*4);
            float4 r1 = *(const float4*)(rowbias + (size_t)row*ldc + bn + 64 + tx*4);
            o0.x+=r0.x; o0.y+=r0.y; o0.z+=r0.z; o0.w+=r0.w;
            o1.x+=r1.x; o1.y+=r1.y; o1.z+=r1.z; o1.w+=r1.w;
        }
        if (RELU){
            o0.x=fmaxf(o0.x,0.f); o0.y=fmaxf(o0.y,0.f); o0.z=fmaxf(o0.z,0.f); o0.w=fmaxf(o0.w,0.f);
            o1.x=fmaxf(o1.x,0.f); o1.y=fmaxf(o1.y,0.f); o1.z=fmaxf(o1.z,0.f); o1.w=fmaxf(o1.w,0.f);
        }
        if (OM == 0){
            *(float4*)(C + (size_t)row*ldc + bn + tx*4)      = o0;
            *(float4*)(C + (size_t)row*ldc + bn + 64 + tx*4) = o1;
        } else if (OM == 2){
            *(uint2*)(Chi + (size_t)row*ldc + bn + tx*4)      = make_uint2(packbf(o0.x,o0.y), packbf(o0.z,o0.w));
            *(uint2*)(Chi + (size_t)row*ldc + bn + 64 + tx*4) = make_uint2(packbf(o1.x,o1.y), packbf(o1.z,o1.w));
        } else {
            float v[8] = {o0.x,o0.y,o0.z,o0.w,o1.x,o1.y,o1.z,o1.w};
            float h[8], l[8];
            #pragma unroll
            for (int q=0;q<8;q++){
                __nv_bfloat16 hb = __float2bfloat16(v[q]);
                h[q] = __bfloat162float(hb); l[q] = v[q]-h[q];
            }
            *(uint2*)(Chi + (size_t)row*ldc + bn + tx*4)      = make_uint2(packbf(h[0],h[1]), packbf(h[2],h[3]));
            *(uint2*)(Chi + (size_t)row*ldc + bn + 64 + tx*4) = make_uint2(packbf(h[4],h[5]), packbf(h[6],h[7]));
            *(uint2*)(Clo + (size_t)row*ldc + bn + tx*4)      = make_uint2(packbf(l[0],l[1]), packbf(l[2],l[3]));
            *(uint2*)(Clo + (size_t)row*ldc + bn + 64 + tx*4) = make_uint2(packbf(l[4],l[5]), packbf(l[6],l[7]));
        }
    }
}

// ---------------- HMMA bf16 split GEMM (R8/R12-proven inner loop) ------------
// TERMS=3: (Ahi+Alo)@(Bhi+Blo)^T; TERMS=1: Ahi@Bhi^T only.
// OMODE: 0 = fp32 out, 1 = bf16 hi/lo split out, 2 = bf16 hi only.
// RBMODE: 0 = none, 2 = generate rowbias from c4 @ iw1[768:772] in epilogue.
__device__ __forceinline__ void mma16816(float* c, const unsigned* a, unsigned b0, unsigned b1){
    asm volatile(
        "mma.sync.aligned.m16n8k16.row.col.f32.bf16.bf16.f32 "
        "{%0,%1,%2,%3}, {%4,%5,%6,%7}, {%8,%9}, {%0,%1,%2,%3};"
        : "+f"(c[0]), "+f"(c[1]), "+f"(c[2]), "+f"(c[3])
        : "r"(a[0]), "r"(a[1]), "r"(a[2]), "r"(a[3]), "r"(b0), "r"(b1));
}

template<bool RELU, int RBMODE, int OMODE, int TERMS>
__global__ __launch_bounds__(256,2) void hgemm(
    const __nv_bfloat16* __restrict__ Ahi, const __nv_bfloat16* __restrict__ Alo,
    const __nv_bfloat16* __restrict__ Bhi, const __nv_bfloat16* __restrict__ Blo,
    const float* __restrict__ bias,
    const float* __restrict__ c4g, const float* __restrict__ iw1g,
    __nv_bfloat16* __restrict__ Chi, __nv_bfloat16* __restrict__ Clo,
    float* __restrict__ Cf, int ldc, int K)
{
    __shared__ __nv_bfloat16 As[2][128][40];
    __shared__ __nv_bfloat16 Bs[2][128][40];
    const int tid  = threadIdx.x;
    const int wid  = tid >> 5, lane = tid & 31;
    const int g    = lane >> 2, tg = lane & 3;
    const int bm   = blockIdx.y * 128, bn = blockIdx.x * 128;
    const int wm   = (wid & 3) * 32, wn = (wid >> 2) * 64;
    const int rowA = tid >> 2;
    const int kq   = (tid & 3) * 8;

    const int nk  = K >> 5;
    const int nch = TERMS * nk;

    float acc[2][8][4];
    #pragma unroll
    for (int mi=0;mi<2;mi++)
        #pragma unroll
        for (int ni=0;ni<8;ni++)
            #pragma unroll
            for (int q=0;q<4;q++) acc[mi][ni][q] = 0.f;

    uint4 a0v,a1v,b0v,b1v;
    auto ldchunk = [&](int c){
        int term = c / nk, kc = c - term*nk;
        const __nv_bfloat16* Ab = (term<2) ? Ahi : Alo;
        const __nv_bfloat16* Bb = (term==1) ? Blo : Bhi;
        const __nv_bfloat16* ap = Ab + (size_t)(bm+rowA)*K + kc*32 + kq;
        const __nv_bfloat16* bp = Bb + (size_t)(bn+rowA)*K + kc*32 + kq;
        a0v = *(const uint4*)ap;  a1v = *(const uint4*)(ap + (size_t)64*K);
        b0v = *(const uint4*)bp;  b1v = *(const uint4*)(bp + (size_t)64*K);
    };
    auto stchunk = [&](int buf){
        *(uint4*)&As[buf][rowA][kq]    = a0v;
        *(uint4*)&As[buf][rowA+64][kq] = a1v;
        *(uint4*)&Bs[buf][rowA][kq]    = b0v;
        *(uint4*)&Bs[buf][rowA+64][kq] = b1v;
    };

    ldchunk(0); stchunk(0);
    __syncthreads();

    for (int c=0; c<nch; c++){
        const int buf = c & 1;
        const bool has = (c+1 < nch);
        if (has) ldchunk(c+1);
        #pragma unroll
        for (int kk=0; kk<32; kk+=16){
            unsigned af[2][4];
            #pragma unroll
            for (int mi=0;mi<2;mi++){
                const int rb0 = wm + mi*16 + g;
                af[mi][0] = *(const unsigned*)&As[buf][rb0  ][kk + tg*2];
                af[mi][1] = *(const unsigned*)&As[buf][rb0+8][kk + tg*2];
                af[mi][2] = *(const unsigned*)&As[buf][rb0  ][kk + 8 + tg*2];
                af[mi][3] = *(const unsigned*)&As[buf][rb0+8][kk + 8 + tg*2];
            }
            #pragma unroll
            for (int ni=0;ni<8;ni++){
                const int nr = wn + ni*8 + g;
                unsigned bw0 = *(const unsigned*)&Bs[buf][nr][kk + tg*2];
                unsigned bw1 = *(const unsigned*)&Bs[buf][nr][kk + 8 + tg*2];
                mma16816(acc[0][ni], af[0], bw0, bw1);
                mma16816(acc[1][ni], af[1], bw0, bw1);
            }
        }
        if (has) stchunk(buf ^ 1);
        __syncthreads();
    }

    // epilogue
    #pragma unroll
    for (int mi=0;mi<2;mi++){
        const int ra = bm + wm + mi*16 + g;
        const int rb_ = ra + 8;
        float4 ca, cb;
        if (RBMODE == 2){
            ca = *(const float4*)(c4g + (size_t)ra*4);
            cb = *(const float4*)(c4g + (size_t)rb_*4);
        }
        #pragma unroll
        for (int ni=0;ni<8;ni++){
            const int col = bn + wn + ni*8 + tg*2;
            float2 bv = *(const float2*)&bias[col];
            float v00 = acc[mi][ni][0] + bv.x, v01 = acc[mi][ni][1] + bv.y;
            float v10 = acc[mi][ni][2] + bv.x, v11 = acc[mi][ni][3] + bv.y;
            if (RBMODE == 2){
                float2 r0 = *(const float2*)(iw1g + (size_t)768*256 + col);
                float2 r1 = *(const float2*)(iw1g + (size_t)769*256 + col);
                float2 r2 = *(const float2*)(iw1g + (size_t)770*256 + col);
                float2 r3 = *(const float2*)(iw1g + (size_t)771*256 + col);
                v00 += ca.x*r0.x + ca.y*r1.x + ca.z*r2.x + ca.w*r3.x;
                v01 += ca.x*r0.y + ca.y*r1.y + ca.z*r2.y + ca.w*r3.y;
                v10 += cb.x*r0.x + cb.y*r1.x + cb.z*r2.x + cb.w*r3.x;
                v11 += cb.x*r0.y + cb.y*r1.y + cb.z*r2.y + cb.w*r3.y;
            }
            if (RELU){
                v00=fmaxf(v00,0.f); v01=fmaxf(v01,0.f);
                v10=fmaxf(v10,0.f); v11=fmaxf(v11,0.f);
            }
            if (OMODE == 0){
                *(float2*)&Cf[(size_t)ra*ldc + col]  = make_float2(v00,v01);
                *(float2*)&Cf[(size_t)rb_*ldc + col] = make_float2(v10,v11);
            } else if (OMODE == 2){
                *(unsigned*)&Chi[(size_t)ra*ldc + col]  = packbf(v00,v01);
                *(unsigned*)&Chi[(size_t)rb_*ldc + col] = packbf(v10,v11);
            } else {
                float h00=__bfloat162float(__float2bfloat16(v00));
                float h01=__bfloat162float(__float2bfloat16(v01));
                float h10=__bfloat162float(__float2bfloat16(v10));
                float h11=__bfloat162float(__float2bfloat16(v11));
                *(unsigned*)&Chi[(size_t)ra*ldc + col]  = packbf(h00,h01);
                *(unsigned*)&Chi[(size_t)rb_*ldc + col] = packbf(h10,h11);
                *(unsigned*)&Clo[(size_t)ra*ldc + col]  = packbf(v00-h00, v01-h01);
                *(unsigned*)&Clo[(size_t)rb_*ldc + col] = packbf(v10-h10, v11-h11);
            }
        }
    }
}

// ---------------- LayerNorm over rows of 256 ---------------------------------
// LMODE: 0 fp32 out, 2 bf16 hi-only out
template<int LMODE>
__global__ void ln_kernel(const float* __restrict__ z, const float* __restrict__ gg,
                          const float* __restrict__ bb,
                          __nv_bfloat16* __restrict__ oh, float* __restrict__ of)
{
    int row  = blockIdx.x*8 + (threadIdx.x>>5);
    int lane = threadIdx.x & 31;
    const float* rr = z + (size_t)row*256 + lane*8;
    float v[8];
    float4 p0 = *(const float4*)rr;
    float4 p1 = *(const float4*)(rr+4);
    v[0]=p0.x;v[1]=p0.y;v[2]=p0.z;v[3]=p0.w;v[4]=p1.x;v[5]=p1.y;v[6]=p1.z;v[7]=p1.w;
    float s=0.f;
    #pragma unroll
    for (int j=0;j<8;j++) s+=v[j];
    #pragma unroll
    for (int off=16;off>0;off>>=1) s += __shfl_xor_sync(0xffffffffu, s, off);
    float mu = s * (1.f/256.f);
    float q=0.f;
    #pragma unroll
    for (int j=0;j<8;j++){ float d=v[j]-mu; q+=d*d; }
    #pragma unroll
    for (int off=16;off>0;off>>=1) q += __shfl_xor_sync(0xffffffffu, q, off);
    float inv = rsqrtf(q*(1.f/256.f) + 1e-5f);
    size_t off = (size_t)row*256 + lane*8;
    if (LMODE == 2){
        float h[8];
        #pragma unroll
        for (int j=0;j<8;j++)
            h[j] = (v[j]-mu)*inv*gg[lane*8+j] + bb[lane*8+j];
        *(uint4*)(oh+off) = make_uint4(packbf(h[0],h[1]),packbf(h[2],h[3]),packbf(h[4],h[5]),packbf(h[6],h[7]));
    } else {
        #pragma unroll
        for (int j=0;j<8;j++)
            of[off+j] = (v[j]-mu)*inv*gg[lane*8+j] + bb[lane*8+j];
    }
}

// ---------------- importance scalar ------------------------------------------
__global__ void imp_kernel(const float* __restrict__ z, const float* __restrict__ iw3,
                           const float* __restrict__ ib3, float* __restrict__ imp)
{
    int row  = blockIdx.x*8 + (threadIdx.x>>5);
    int lane = threadIdx.x & 31;
    const float* r = z + (size_t)row*256 + lane*8;
    float s = 0.f;
    #pragma unroll
    for (int j=0;j<8;j++) s += r[j]*iw3[lane*8+j];
    #pragma unroll
    for (int off=16;off>0;off>>=1) s += __shfl_xor_sync(0xffffffffu, s, off);
    if (lane==0) imp[row] = s + ib3[0];
}

// ---------------- per-batch top-256 candidates (approx keys) ------------------
__global__ void topk256_kernel(const float* __restrict__ imp, const float* __restrict__ noise,
                               int* __restrict__ cand)
{
    extern __shared__ unsigned skey[];
    __shared__ unsigned hist[256];
    __shared__ unsigned s_prefix, s_mask;
    __shared__ int s_rem, s_cnt, s_eqcnt;
    __shared__ int eqbuf[512];
    const int b = blockIdx.x;
    const int tid = threadIdx.x;
    for (int i=tid;i<PB;i+=1024)
        skey[i] = f2u(imp[b*PB+i] + noise[b*PB+i]);
    if (tid==0){ s_prefix=0u; s_mask=0u; s_rem=KSEL; }
    __syncthreads();
    for (int round=0; round<4; round++){
        const int shift = 24 - 8*round;
        if (tid<256) hist[tid]=0u;
        __syncthreads();
        unsigned mask = s_mask, prefix = s_prefix;
        for (int i=tid;i<PB;i+=1024){
            unsigned k = skey[i];
            if ((k & mask) == prefix) atomicAdd(&hist[(k>>shift)&255u], 1u);
        }
        __syncthreads();
        if (tid==0){
            int rem = s_rem; unsigned cum=0; int bsel=0;
            for (int bin=255; bin>=0; bin--){
                if (cum + hist[bin] >= (unsigned)rem){ bsel=bin; break; }
                cum += hist[bin];
            }
            s_rem    = rem - (int)cum;
            s_prefix = prefix | ((unsigned)bsel << shift);
            s_mask   = mask   | (0xFFu << shift);
        }
        __syncthreads();
    }
    const unsigned kth = s_prefix;
    const int rEq = s_rem;
    if (tid==0){ s_cnt=0; s_eqcnt=0; }
    __syncthreads();
    for (int i=tid;i<PB;i+=1024){
        unsigned k = skey[i];
        if (k > kth){
            int p = atomicAdd(&s_cnt,1);
            cand[b*KSEL+p] = i;
        } else if (k == kth){
            int p = atomicAdd(&s_eqcnt,1);
            if (p < 512) eqbuf[p] = i;
        }
    }
    __syncthreads();
    if (tid==0){
        int base = s_cnt;
        for (int a=0;a<rEq;a++) cand[b*KSEL+base+a] = eqbuf[a];
    }
}

// ---------------- gather candidate inputs + compute rbc -----------------------
__global__ void cand_gather(const int* __restrict__ cand, const float* __restrict__ iw1,
                            float* __restrict__ xc, float* __restrict__ rbc)
{
    const int j = blockIdx.x;
    const int b = j >> 8;
    const int i = cand[j];
    const int gidx = b*PB + i;
    const int t = threadIdx.x;            // 64
    if (t < 2) ((float4*)xc)[j*2+t] = ((const float4*)g_x8)[(size_t)gidx*2+t];
    const int n = t*4;
    float4 c  = *(const float4*)(g_c4 + (size_t)gidx*4);
    float4 r0 = *(const float4*)(iw1 + (size_t)768*256 + n);
    float4 r1 = *(const float4*)(iw1 + (size_t)769*256 + n);
    float4 r2 = *(const float4*)(iw1 + (size_t)770*256 + n);
    float4 r3 = *(const float4*)(iw1 + (size_t)771*256 + n);
    float4 o;
    o.x = c.x*r0.x + c.y*r1.x + c.z*r2.x + c.w*r3.x;
    o.y = c.x*r0.y + c.y*r1.y + c.z*r2.y + c.w*r3.y;
    o.z = c.x*r0.z + c.y*r1.z + c.z*r2.z + c.w*r3.z;
    o.w = c.x*r0.w + c.y*r1.w + c.z*r2.w + c.w*r3.w;
    *(float4*)(rbc + (size_t)j*256 + n) = o;
}

// ---------------- exact top-128 among candidates ------------------------------
__global__ void topk_final(const float* __restrict__ impc, const float* __restrict__ noise,
                           const int* __restrict__ cand, const float* __restrict__ c4,
                           float* __restrict__ cent)
{
    __shared__ unsigned long long s[KSEL];
    const int b = blockIdx.x, t = threadIdx.x;
    const int i = cand[b*KSEL+t];
    float v = impc[b*KSEL+t] + noise[b*PB+i];
    s[t] = ((unsigned long long)(~f2u(v)) << 32) | (unsigned)i;
    __syncthreads();
    for (int ksz=2; ksz<=KSEL; ksz<<=1){
        for (int j=ksz>>1; j>0; j>>=1){
            int ixj = t ^ j;
            if (ixj > t){
                unsigned long long a = s[t], c = s[ixj];
                bool up = ((t & ksz) == 0);
                if (up ? (a > c) : (a < c)){ s[t]=c; s[ixj]=a; }
            }
            __syncthreads();
        }
    }
    if (t < MTOK){
        int i2 = (unsigned)(s[t] & 0xffffffffu);
        #pragma unroll
        for (int q=0;q<4;q++) cent[(b*MTOK+t)*4+q] = c4[(size_t)(b*PB+i2)*4+q];
    }
}

// ---------------- stable sort of 128 cents by t -------------------------------
__global__ void sortt_kernel(const float* __restrict__ cent, int* __restrict__ order)
{
    __shared__ unsigned long long s[128];
    const int b = blockIdx.x, tid = threadIdx.x;
    float t = cent[(b*MTOK+tid)*4+3];
    s[tid] = ((unsigned long long)f2u(t) << 32) | (unsigned)tid;
    __syncthreads();
    for (int ksz=2; ksz<=128; ksz<<=1){
        for (int j=ksz>>1; j>0; j>>=1){
            int ixj = tid ^ j;
            if (ixj > tid){
                unsigned long long a = s[tid], c = s[ixj];
                bool up = ((tid & ksz) == 0);
                if (up ? (a > c) : (a < c)){ s[tid]=c; s[ixj]=a; }
            }
            __syncthreads();
        }
    }
    order[b*MTOK+tid] = (int)(s[tid] & 0xffffffffu);
}

// ---------------- brute-force 16-NN -------------------------------------------
__global__ void knn_kernel(const float* __restrict__ c4, const float* __restrict__ cent,
                           int* __restrict__ knn)
{
    __shared__ unsigned long long lists[128][KNN];
    const int bm = blockIdx.x;
    const int b  = bm >> 7;
    const int tid = threadIdx.x;
    const float cx = cent[bm*4+0], cy = cent[bm*4+1], cz = cent[bm*4+2], ct = cent[bm*4+3];
    unsigned long long loc[KNN];
    #pragma unroll
    for (int q=0;q<KNN;q++) loc[q] = ~0ull;
    const float* cb = c4 + (size_t)b*PB*4;
    for (int i=tid;i<PB;i+=128){
        float4 p = *(const float4*)(cb + (size_t)i*4);
        float dx=p.x-cx, dy=p.y-cy, dz=p.z-cz, dt=p.w-ct;
        float d2 = dx*dx + dy*dy + dz*dz + dt*dt;
        unsigned long long key = ((unsigned long long)(__float_as_uint(d2)|0x80000000u) << 32) | (unsigned)i;
        if (key < loc[KNN-1]){
            loc[KNN-1] = key;
            #pragma unroll
            for (int q=KNN-1;q>0;q--){
                if (loc[q] < loc[q-1]){ unsigned long long t=loc[q]; loc[q]=loc[q-1]; loc[q-1]=t; }
            }
        }
    }
    #pragma unroll
    for (int q=0;q<KNN;q++) lists[tid][q]=loc[q];
    __syncthreads();
    for (int sgap=64; sgap>0; sgap>>=1){
        if (tid < sgap){
            unsigned long long out[KNN];
            int i1=0, i2=0;
            #pragma unroll
            for (int q=0;q<KNN;q++){
                unsigned long long a=lists[tid][i1], c=lists[tid+sgap][i2];
                if (a<=c){ out[q]=a; i1++; } else { out[q]=c; i2++; }
            }
            #pragma unroll
            for (int q=0;q<KNN;q++) lists[tid][q]=out[q];
        }
        __syncthreads();
    }
    if (tid < KNN) knn[bm*KNN+tid] = (int)(lists[0][tid] & 0xffffffffu);
}

// ---------------- gather x8 rows of knn neighbors -----------------------------
__global__ void gatherx_kernel(const int* __restrict__ knn, float* __restrict__ gx)
{
    const int r = blockIdx.x*256 + threadIdx.x;   // 0..NGATH-1
    const int bm = r / KNN;
    const int b  = bm >> 7;
    const int nb = b*PB + knn[r];
    ((float4*)gx)[(size_t)r*2+0] = ((const float4*)g_x8)[(size_t)nb*2+0];
    ((float4*)gx)[(size_t)r*2+1] = ((const float4*)g_x8)[(size_t)nb*2+1];
}

// ---------------- max pool over groups of 16 ----------------------------------
__global__ void pool_kernel(const float* __restrict__ pfg, float* __restrict__ pooled)
{
    const int bm = blockIdx.x;
    const int tid = threadIdx.x;
    for (int c=tid;c<TOKD;c+=256){
        float m = -3.402823466e38f;
        #pragma unroll
        for (int q=0;q<KNN;q++)
            m = fmaxf(m, pfg[(size_t)(bm*KNN+q)*768 + c]);
        pooled[(size_t)bm*TOKD + c] = m;
    }
}

// ---------------- scatter to output in time order -----------------------------
__global__ void out_kernel(const float* __restrict__ tok, const float* __restrict__ cent,
                           const int* __restrict__ order, float* __restrict__ out)
{
    const int bj = blockIdx.x;
    const int b  = bj >> 7;
    const int o  = order[bj];
    const float* src = tok + (size_t)(b*MTOK+o)*TOKD;
    float* dst = out + (size_t)bj*TOKD;
    for (int c=threadIdx.x;c<TOKD;c+=256) dst[c]=src[c];
    if (threadIdx.x < 4) out[(size_t)BATCH*MTOK*TOKD + bj*4 + threadIdx.x] = cent[(b*MTOK+o)*4+threadIdx.x];
    if (threadIdx.x == 4) out[(size_t)BATCH*MTOK*TOKD + (size_t)BATCH*MTOK*4 + bj] = 1.0f;
}

// ---------------- launch ------------------------------------------------------
extern "C" void kernel_launch(void* const* d_in, const int* in_sizes, int n_in,
                              void* d_out, int out_size)
{
    (void)in_sizes; (void)n_in; (void)out_size;
    const float* coords = (const float*)d_in[0];
    const float* feats  = (const float*)d_in[1];
    const float* w1  = (const float*)d_in[3];  const float* b1  = (const float*)d_in[4];
    const float* w2  = (const float*)d_in[5];  const float* b2  = (const float*)d_in[6];
    const float* w3  = (const float*)d_in[7];  const float* b3  = (const float*)d_in[8];
    const float* w4  = (const float*)d_in[9];  const float* b4  = (const float*)d_in[10];
    const float* iw1 = (const float*)d_in[11]; const float* ib1 = (const float*)d_in[12];
    const float* lng = (const float*)d_in[13]; const float* lnb = (const float*)d_in[14];
    const float* iw2 = (const float*)d_in[15]; const float* ib2 = (const float*)d_in[16];
    const float* iw3 = (const float*)d_in[17]; const float* ib3 = (const float*)d_in[18];
    const float* nw1 = (const float*)d_in[19]; const float* nb1 = (const float*)d_in[20];
    const float* nw2 = (const float*)d_in[21]; const float* nb2 = (const float*)d_in[22];
    const float* noise = (const float*)d_in[23];

    void *px8,*pw1p,*pc4,*ph1h,*ph2h,*ph3h,*pwp,*pbp,*pz0;
    void *pz1,*pz2h,*pz3,*pimp,*pcand,*pxc,*prbc,*ph1c,*ph2c,*ph3c,*pz1c,*pz2c,*pz3c,*pimpc;
    void *pcent,*pord,*pknn,*pgx,*ph1gh,*ph1gl,*ph2gh,*ph2gl,*pgh,*pgl,*ppfg,*ppool,*pt1,*ptok;
    void *pw2h,*pw2l,*pw3h,*pw3l,*pw4h,*pw4l,*pwph,*pwpl,*piw2h,*piw2l;
    cudaGetSymbolAddress(&px8,g_x8);     cudaGetSymbolAddress(&pw1p,g_w1p);
    cudaGetSymbolAddress(&pc4,g_c4);
    cudaGetSymbolAddress(&ph1h,g_h1h);
    cudaGetSymbolAddress(&ph2h,g_h2h);   cudaGetSymbolAddress(&ph3h,g_h3h);
    cudaGetSymbolAddress(&pwp,g_wp);     cudaGetSymbolAddress(&pbp,g_biasp);
    cudaGetSymbolAddress(&pz0,g_zero256);
    cudaGetSymbolAddress(&pz1,g_z1);     cudaGetSymbolAddress(&pz2h,g_z2h);
    cudaGetSymbolAddress(&pz3,g_z3);
    cudaGetSymbolAddress(&pimp,g_imp);   cudaGetSymbolAddress(&pcand,g_cand);
    cudaGetSymbolAddress(&pxc,g_xc);     cudaGetSymbolAddress(&prbc,g_rbc);
    cudaGetSymbolAddress(&ph1c,g_h1c);   cudaGetSymbolAddress(&ph2c,g_h2c);
    cudaGetSymbolAddress(&ph3c,g_h3c);   cudaGetSymbolAddress(&pz1c,g_z1c);
    cudaGetSymbolAddress(&pz2c,g_z2c);   cudaGetSymbolAddress(&pz3c,g_z3c);
    cudaGetSymbolAddress(&pimpc,g_impc);
    cudaGetSymbolAddress(&pcent,g_cent); cudaGetSymbolAddress(&pord,g_order);
    cudaGetSymbolAddress(&pknn,g_knn);   cudaGetSymbolAddress(&pgx,g_gx);
    cudaGetSymbolAddress(&ph1gh,g_h1gh); cudaGetSymbolAddress(&ph1gl,g_h1gl);
    cudaGetSymbolAddress(&ph2gh,g_h2gh); cudaGetSymbolAddress(&ph2gl,g_h2gl);
    cudaGetSymbolAddress(&pgh,g_gh);     cudaGetSymbolAddress(&pgl,g_gl);
    cudaGetSymbolAddress(&ppfg,g_pfg);   cudaGetSymbolAddress(&ppool,g_pooled);
    cudaGetSymbolAddress(&pt1,g_t1);     cudaGetSymbolAddress(&ptok,g_tok);
    cudaGetSymbolAddress(&pw2h,g_w2th);  cudaGetSymbolAddress(&pw2l,g_w2tl);
    cudaGetSymbolAddress(&pw3h,g_w3th);  cudaGetSymbolAddress(&pw3l,g_w3tl);
    cudaGetSymbolAddress(&pw4h,g_w4th);  cudaGetSymbolAddress(&pw4l,g_w4tl);
    cudaGetSymbolAddress(&pwph,g_wpth);  cudaGetSymbolAddress(&pwpl,g_wptl);
    cudaGetSymbolAddress(&piw2h,g_iw2th);cudaGetSymbolAddress(&piw2l,g_iw2tl);

    cudaFuncSetAttribute(topk256_kernel, cudaFuncAttributeMaxDynamicSharedMemorySize, PB*4);

    prep_points<<<NPTS/256, 256>>>(coords, feats);
    prep_w<<<8, 256>>>(w1);
    biasp_init<<<1,256>>>(ib1, (float*)pbp);
    biasp_acc<<<8,256>>>(b4, iw1, (float*)pbp);
    sgemm128<false,false,0><<<dim3(2,6),256>>>(w4, 768, iw1, 256, (const float*)pz0,
        nullptr, (float*)pwp, nullptr, nullptr, 256, 768);
    conv_wt<<<(512*256+255)/256,256>>>(w2, 256, 512, (__nv_bfloat16*)pw2h, (__nv_bfloat16*)pw2l);
    conv_wt<<<(768*512+255)/256,256>>>(w3, 512, 768, (__nv_bfloat16*)pw3h, (__nv_bfloat16*)pw3l);
    conv_wt<<<(768*768+255)/256,256>>>(w4, 768, 768, (__nv_bfloat16*)pw4h, (__nv_bfloat16*)pw4l);
    conv_wt<<<(256*768+255)/256,256>>>((const float*)pwp, 768, 256, (__nv_bfloat16*)pwph, (__nv_bfloat16*)pwpl);
    conv_wt<<<(256*256+255)/256,256>>>(iw2, 256, 256, (__nv_bfloat16*)piw2h, (__nv_bfloat16*)piw2l);

    // L1 scalar -> h1 hi-only (full points; 1-term trunk never reads lo)
    sgemm128<true,false,2><<<dim3(2,1024),256>>>((const float*)px8, 8, (const float*)pw1p, 256, b1,
        nullptr, nullptr, (__nv_bfloat16*)ph1h, nullptr, 256, 8);
    // trunk 1-term (importance-only precision), bf16-hi outputs
    hgemm<true,0,2,1><<<dim3(4,1024),256>>>((const __nv_bfloat16*)ph1h, nullptr,
        (const __nv_bfloat16*)pw2h,(const __nv_bfloat16*)pw2l, b2, nullptr, nullptr,
        (__nv_bfloat16*)ph2h, nullptr, nullptr, 512, 256);
    hgemm<true,0,2,1><<<dim3(6,1024),256>>>((const __nv_bfloat16*)ph2h, nullptr,
        (const __nv_bfloat16*)pw3h,(const __nv_bfloat16*)pw3l, b3, nullptr, nullptr,
        (__nv_bfloat16*)ph3h, nullptr, nullptr, 768, 512);
    // importance branch (1-term) with rowbias generated in epilogue from c4 @ iw1[768:772]
    hgemm<true,2,0,1><<<dim3(2,1024),256>>>((const __nv_bfloat16*)ph3h, nullptr,
        (const __nv_bfloat16*)pwph,(const __nv_bfloat16*)pwpl, (const float*)pbp,
        (const float*)pc4, iw1,
        nullptr, nullptr, (float*)pz1, 256, 768);
    ln_kernel<2><<<NPTS/8,256>>>((const float*)pz1, lng, lnb, (__nv_bfloat16*)pz2h, nullptr);
    hgemm<true,0,0,1><<<dim3(2,1024),256>>>((const __nv_bfloat16*)pz2h, nullptr,
        (const __nv_bfloat16*)piw2h,(const __nv_bfloat16*)piw2l, ib2, nullptr, nullptr,
        nullptr, nullptr, (float*)pz3, 256, 256);
    imp_kernel<<<NPTS/8,256>>>((const float*)pz3, iw3, ib3, (float*)pimp);

    // approx top-256 candidates, then exact scalar refinement
    topk256_kernel<<<BATCH,1024,PB*4>>>((const float*)pimp, noise, (int*)pcand);
    cand_gather<<<NCAND,64>>>((const int*)pcand, iw1, (float*)pxc, (float*)prbc);
    sgemm128<true,false,0><<<dim3(2,16),256>>>((const float*)pxc, 8, (const float*)pw1p, 256, b1,
        nullptr, (float*)ph1c, nullptr, nullptr, 256, 8);
    sgemm128<true,false,0><<<dim3(4,16),256>>>((const float*)ph1c, 256, w2, 512, b2,
        nullptr, (float*)ph2c, nullptr, nullptr, 512, 256);
    sgemm128<true,false,0><<<dim3(6,16),256>>>((const float*)ph2c, 512, w3, 768, b3,
        nullptr, (float*)ph3c, nullptr, nullptr, 768, 512);
    sgemm128<true,true,0><<<dim3(2,16),256>>>((const float*)ph3c, 768, (const float*)pwp, 256,
        (const float*)pbp, (const float*)prbc, (float*)pz1c, nullptr, nullptr, 256, 768);
    ln_kernel<0><<<NCAND/8,256>>>((const float*)pz1c, lng, lnb, nullptr, (float*)pz2c);
    sgemm128<true,false,0><<<dim3(2,16),256>>>((const float*)pz2c, 256, iw2, 256, ib2,
        nullptr, (float*)pz3c, nullptr, nullptr, 256, 256);
    imp_kernel<<<NCAND/8,256>>>((const float*)pz3c, iw3, ib3, (float*)pimpc);
    topk_final<<<BATCH,KSEL>>>((const float*)pimpc, noise, (const int*)pcand,
                               (const float*)pc4, (float*)pcent);

    // neighborhoods (coordinates only)
    sortt_kernel<<<BATCH,128>>>((const float*)pcent, (int*)pord);
    knn_kernel<<<BATCH*MTOK,128>>>((const float*)pc4, (const float*)pcent, (int*)pknn);

    // neighbor trunk recompute at full (3-term) precision: 16384 rows
    gatherx_kernel<<<NGATH/256,256>>>((const int*)pknn, (float*)pgx);
    sgemm128<true,false,1><<<dim3(2,NGATH/128),256>>>((const float*)pgx, 8, (const float*)pw1p, 256, b1,
        nullptr, nullptr, (__nv_bfloat16*)ph1gh, (__nv_bfloat16*)ph1gl, 256, 8);
    hgemm<true,0,1,3><<<dim3(4,NGATH/128),256>>>((const __nv_bfloat16*)ph1gh,(const __nv_bfloat16*)ph1gl,
        (const __nv_bfloat16*)pw2h,(const __nv_bfloat16*)pw2l, b2, nullptr, nullptr,
        (__nv_bfloat16*)ph2gh,(__nv_bfloat16*)ph2gl, nullptr, 512, 256);
    hgemm<true,0,1,3><<<dim3(6,NGATH/128),256>>>((const __nv_bfloat16*)ph2gh,(const __nv_bfloat16*)ph2gl,
        (const __nv_bfloat16*)pw3h,(const __nv_bfloat16*)pw3l, b3, nullptr, nullptr,
        (__nv_bfloat16*)pgh,(__nv_bfloat16*)pgl, nullptr, 768, 512);
    hgemm<false,0,0,3><<<dim3(6,NGATH/128),256>>>((const __nv_bfloat16*)pgh,(const __nv_bfloat16*)pgl,
        (const __nv_bfloat16*)pw4h,(const __nv_bfloat16*)pw4l, b4, nullptr, nullptr,
        nullptr, nullptr, (float*)ppfg, 768, 768);
    pool_kernel<<<BATCH*MTOK,256>>>((const float*)ppfg, (float*)ppool);

    // token MLP scalar fp32
    sgemm128<true ,false,0><<<dim3(6,8),256>>>((const float*)ppool, 768, nw1, 768, nb1,
        nullptr, (float*)pt1, nullptr, nullptr, 768, 768);
    sgemm128<false,false,0><<<dim3(6,8),256>>>((const float*)pt1, 768, nw2, 768, nb2,
        nullptr, (float*)ptok, nullptr, nullptr, 768, 768);

    out_kernel<<<BATCH*MTOK,256>>>((const float*)ptok, (const float*)pcent, (const int*)pord, (float*)d_out);
}

// round 15
// speedup vs baseline: 1.0741x; 1.0330x over previous
#include <cuda_runtime.h>
#include <cuda_bf16.h>
#include <math.h>
#include <stdint.h>

#define NPTS   131072
#define PB     16384
#define BATCH  8
#define MTOK   128
#define KNN    16
#define TOKD   768
#define NGATH  (BATCH*MTOK*KNN)   // 16384 gathered neighbor rows
#define KSEL   256                // candidate pool per batch
#define NCAND  (BATCH*KSEL)       // 2048

// ---------------- scratch (device globals; no allocs allowed) ----------------
__device__ __align__(16) float g_x8[NPTS*8];
__device__ __align__(16) float g_w1p[8*256];
__device__ __align__(16) float g_c4[NPTS*4];
__device__ __align__(16) __nv_bfloat16 g_h1h[(size_t)NPTS*256];
__device__ __align__(16) __nv_bfloat16 g_h2h[(size_t)NPTS*512];
__device__ __align__(16) __nv_bfloat16 g_h3h[(size_t)NPTS*768];
__device__ __align__(16) float g_wp[768*256];          // w4 @ iw1[0:768]
__device__ __align__(16) float g_biasp[256];
__device__ __align__(16) float g_zero256[256];         // stays zero
__device__ __align__(16) float g_z1[(size_t)NPTS*256];
__device__ __align__(16) __nv_bfloat16 g_z2h[(size_t)NPTS*256];
__device__ float g_imp[NPTS];
// split weights [N][K] bf16 hi/lo
__device__ __align__(16) __nv_bfloat16 g_w2th[512*256],  g_w2tl[512*256];
__device__ __align__(16) __nv_bfloat16 g_w3th[768*512],  g_w3tl[768*512];
__device__ __align__(16) __nv_bfloat16 g_w4th[768*768],  g_w4tl[768*768];
__device__ __align__(16) __nv_bfloat16 g_wpth[256*768],  g_wptl[256*768];
__device__ __align__(16) __nv_bfloat16 g_iw2th[256*256], g_iw2tl[256*256];
// refinement
__device__ int   g_cand[NCAND];
__device__ __align__(16) float g_xc[NCAND*8];
__device__ __align__(16) float g_rbc[NCAND*256];
__device__ __align__(16) float g_h1c[NCAND*256];
__device__ __align__(16) float g_h2c[NCAND*512];
__device__ __align__(16) float g_h3c[NCAND*768];
__device__ __align__(16) float g_z1c[NCAND*256];
__device__ __align__(16) float g_z2c[NCAND*256];
__device__ __align__(16) float g_z3c[NCAND*256];
__device__ float g_impc[NCAND];
// selection + neighbor recompute
__device__ float g_cent[BATCH*MTOK*4];
__device__ int   g_order[BATCH*MTOK];
__device__ int   g_knn[BATCH*MTOK*KNN];
__device__ __align__(16) float g_gx[NGATH*8];
__device__ __align__(16) __nv_bfloat16 g_h1gh[(size_t)NGATH*256], g_h1gl[(size_t)NGATH*256];
__device__ __align__(16) __nv_bfloat16 g_h2gh[(size_t)NGATH*512], g_h2gl[(size_t)NGATH*512];
__device__ __align__(16) __nv_bfloat16 g_gh[(size_t)NGATH*768], g_gl[(size_t)NGATH*768];
__device__ __align__(16) float g_pfg[(size_t)NGATH*768];
__device__ __align__(16) float g_pooled[BATCH*MTOK*TOKD];
__device__ __align__(16) float g_t1[BATCH*MTOK*TOKD];
__device__ __align__(16) float g_tok[BATCH*MTOK*TOKD];

__device__ __forceinline__ unsigned packbf(float lo, float hi){
    unsigned r; asm("cvt.rn.bf16x2.f32 %0, %2, %1;" : "=r"(r) : "f"(lo), "f"(hi)); return r;
}
__device__ __forceinline__ unsigned f2u(float x){
    unsigned u = __float_as_uint(x);
    return (u & 0x80000000u) ? ~u : (u | 0x80000000u);
}

// ---------------- prep -------------------------------------------------------
__global__ void prep_points(const float* __restrict__ coords,
                            const float* __restrict__ feats)
{
    int i = blockIdx.x*blockDim.x + threadIdx.x;
    if (i >= NPTS) return;
    #pragma unroll
    for (int j=0;j<6;j++) g_x8[i*8+j] = feats[i*6+j];
    g_x8[i*8+6]=0.f; g_x8[i*8+7]=0.f;
    #pragma unroll
    for (int j=0;j<4;j++) g_c4[i*4+j] = coords[i*5+1+j];
}
__global__ void prep_w(const float* __restrict__ w1)
{
    int idx = blockIdx.x*blockDim.x + threadIdx.x;
    if (idx < 8*256) g_w1p[idx] = (idx < 6*256) ? w1[idx] : 0.f;
}
__global__ void biasp_init(const float* __restrict__ ib1, float* __restrict__ bp)
{ bp[threadIdx.x] = ib1[threadIdx.x]; }
__global__ void biasp_acc(const float* __restrict__ b4, const float* __restrict__ iw1,
                          float* __restrict__ bp)
{
    int n = threadIdx.x;
    int j0 = blockIdx.x*96;
    float s = 0.f;
    for (int j=j0;j<j0+96;j++) s += b4[j]*iw1[(size_t)j*256+n];
    atomicAdd(&bp[n], s);
}
__global__ void init_imp(const float* __restrict__ ib3, float* __restrict__ imp)
{
    int i = blockIdx.x*blockDim.x + threadIdx.x;
    if (i < NPTS) imp[i] = ib3[0];
}
__global__ void conv_wt(const float* __restrict__ src, int K, int N,
                        __nv_bfloat16* __restrict__ dh, __nv_bfloat16* __restrict__ dl)
{
    int idx = blockIdx.x*blockDim.x + threadIdx.x;
    if (idx >= N*K) return;
    int n = idx / K, k = idx - n*K;
    float v = src[(size_t)k*N + n];
    __nv_bfloat16 h = __float2bfloat16(v);
    dh[idx] = h;
    dl[idx] = __float2bfloat16(v - __bfloat162float(h));
}

// ---------------- scalar SGEMM (proven core) ---------------------------------
// OM: 0 fp32 out, 1 bf16 hi/lo split out, 2 bf16 hi-only out
template<bool RELU, bool RB, int OM>
__global__ __launch_bounds__(256,2) void sgemm128(
    const float* __restrict__ A, int lda,
    const float* __restrict__ B, int N,
    const float* __restrict__ bias,
    const float* __restrict__ rowbias,
    float* __restrict__ C,
    __nv_bfloat16* __restrict__ Chi, __nv_bfloat16* __restrict__ Clo,
    int ldc, int K)
{
    __shared__ float As[2][8][128];
    __shared__ float Bs[2][8][128];
    const int tid  = threadIdx.x;
    const int bm   = blockIdx.y * 128;
    const int bn   = blockIdx.x * 128;
    const int arow = tid >> 1;
    const int acol = (tid & 1) * 4;
    const int brow = tid >> 5;
    const int bcol = (tid & 31) * 4;
    const int tx   = tid & 15;
    const int ty   = tid >> 4;

    const float* Aptr = A + (size_t)(bm + arow) * lda + acol;
    const float* Bptr = B + (size_t)brow * N + bn + bcol;

    float acc[8][8];
    #pragma unroll
    for (int i=0;i<8;i++)
        #pragma unroll
        for (int j=0;j<8;j++) acc[i][j]=0.f;

    {
        float4 a = *(const float4*)Aptr;
        As[0][acol+0][arow]=a.x; As[0][acol+1][arow]=a.y;
        As[0][acol+2][arow]=a.z; As[0][acol+3][arow]=a.w;
        *(float4*)&Bs[0][brow][bcol] = *(const float4*)Bptr;
    }
    __syncthreads();

    const int ktiles = K >> 3;
    int buf = 0;
    for (int kt=0; kt<ktiles; kt++){
        float4 a, bv;
        const bool has = (kt+1 < ktiles);
        if (has){
            a  = *(const float4*)(Aptr + (kt+1)*8);
            bv = *(const float4*)(Bptr + (size_t)(kt+1)*8*N);
        }
        #pragma unroll
        for (int k=0;k<8;k++){
            float4 a0 = *(const float4*)&As[buf][k][ty*4];
            float4 a1 = *(const float4*)&As[buf][k][64+ty*4];
            float4 b0 = *(const float4*)&Bs[buf][k][tx*4];
            float4 b1 = *(const float4*)&Bs[buf][k][64+tx*4];
            float ar[8] = {a0.x,a0.y,a0.z,a0.w,a1.x,a1.y,a1.z,a1.w};
            float br[8] = {b0.x,b0.y,b0.z,b0.w,b1.x,b1.y,b1.z,b1.w};
            #pragma unroll
            for (int i=0;i<8;i++)
                #pragma unroll
                for (int j=0;j<8;j++)
                    acc[i][j] += ar[i]*br[j];
        }
        if (has){
            const int nb = buf^1;
            As[nb][acol+0][arow]=a.x; As[nb][acol+1][arow]=a.y;
            As[nb][acol+2][arow]=a.z; As[nb][acol+3][arow]=a.w;
            *(float4*)&Bs[nb][brow][bcol] = bv;
        }
        __syncthreads();
        buf ^= 1;
    }

    float4 bv0 = *(const float4*)(bias + bn + tx*4);
    float4 bv1 = *(const float4*)(bias + bn + 64 + tx*4);
    #pragma unroll
    for (int i=0;i<8;i++){
        const int row = bm + ((i<4) ? (ty*4+i) : (64 + ty*4 + i - 4));
        float4 o0, o1;
        o0.x=acc[i][0]+bv0.x; o0.y=acc[i][1]+bv0.y; o0.z=acc[i][2]+bv0.z; o0.w=acc[i][3]+bv0.w;
        o1.x=acc[i][4]+bv1.x; o1.y=acc[i][5]+bv1.y; o1.z=acc[i][6]+bv1.z; o1.w=acc[i][7]+bv1.w;
        if (RB){
            float4 r0 = *(const float4*)(rowbias + (size_t)row*ldc + bn + tx*4);
            float4 r1 = *(const float4*)(rowbias + (size_t)row*ldc + bn + 64 + tx*4);
            o0.x+=r0.x; o0.y+=r0.y; o0.z+=r0.z; o0.w+=r0.w;
            o1.x+=r1.x; o1.y+=r1.y; o1.z+=r1.z; o1.w+=r1.w;
        }
        if (RELU){
            o0.x=fmaxf(o0.x,0.f); o0.y=fmaxf(o0.y,0.f); o0.z=fmaxf(o0.z,0.f); o0.w=fmaxf(o0.w,0.f);
            o1.x=fmaxf(o1.x,0.f); o1.y=fmaxf(o1.y,0.f); o1.z=fmaxf(o1.z,0.f); o1.w=fmaxf(o1.w,0.f);
        }
        if (OM == 0){
            *(float4*)(C + (size_t)row*ldc + bn + tx*4)      = o0;
            *(float4*)(C + (size_t)row*ldc + bn + 64 + tx*4) = o1;
        } else if (OM == 2){
            *(uint2*)(Chi + (size_t)row*ldc + bn + tx*4)      = make_uint2(packbf(o0.x,o0.y), packbf(o0.z,o0.w));
            *(uint2*)(Chi + (size_t)row*ldc + bn + 64 + tx*4) = make_uint2(packbf(o1.x,o1.y), packbf(o1.z,o1.w));
        } else {
            float v[8] = {o0.x,o0.y,o0.z,o0.w,o1.x,o1.y,o1.z,o1.w};
            float h[8], l[8];
            #pragma unroll
            for (int q=0;q<8;q++){
                __nv_bfloat16 hb = __float2bfloat16(v[q]);
                h[q] = __bfloat162float(hb); l[q] = v[q]-h[q];
            }
            *(uint2*)(Chi + (size_t)row*ldc + bn + tx*4)      = make_uint2(packbf(h[0],h[1]), packbf(h[2],h[3]));
            *(uint2*)(Chi + (size_t)row*ldc + bn + 64 + tx*4) = make_uint2(packbf(h[4],h[5]), packbf(h[6],h[7]));
            *(uint2*)(Clo + (size_t)row*ldc + bn + tx*4)      = make_uint2(packbf(l[0],l[1]), packbf(l[2],l[3]));
            *(uint2*)(Clo + (size_t)row*ldc + bn + 64 + tx*4) = make_uint2(packbf(l[4],l[5]), packbf(l[6],l[7]));
        }
    }
}

// ---------------- HMMA bf16 split GEMM (R8/R12-proven inner loop) ------------
// TERMS=3: (Ahi+Alo)@(Bhi+Blo)^T; TERMS=1: Ahi@Bhi^T only.
// OMODE: 0 fp32 out, 1 bf16 hi/lo split out, 2 bf16 hi only,
//        3 fused importance reduce: atomicAdd(Cf[row], sum_col relu(v)*iw3[col]).
// RBMODE: 0 = none, 2 = generate rowbias from c4 @ iw1[768:772] in epilogue.
__device__ __forceinline__ void mma16816(float* c, const unsigned* a, unsigned b0, unsigned b1){
    asm volatile(
        "mma.sync.aligned.m16n8k16.row.col.f32.bf16.bf16.f32 "
        "{%0,%1,%2,%3}, {%4,%5,%6,%7}, {%8,%9}, {%0,%1,%2,%3};"
        : "+f"(c[0]), "+f"(c[1]), "+f"(c[2]), "+f"(c[3])
        : "r"(a[0]), "r"(a[1]), "r"(a[2]), "r"(a[3]), "r"(b0), "r"(b1));
}

template<bool RELU, int RBMODE, int OMODE, int TERMS>
__global__ __launch_bounds__(256,2) void hgemm(
    const __nv_bfloat16* __restrict__ Ahi, const __nv_bfloat16* __restrict__ Alo,
    const __nv_bfloat16* __restrict__ Bhi, const __nv_bfloat16* __restrict__ Blo,
    const float* __restrict__ bias,
    const float* __restrict__ c4g, const float* __restrict__ iw1g,
    const float* __restrict__ iw3g,
    __nv_bfloat16* __restrict__ Chi, __nv_bfloat16* __restrict__ Clo,
    float* __restrict__ Cf, int ldc, int K)
{
    __shared__ __nv_bfloat16 As[2][128][40];
    __shared__ __nv_bfloat16 Bs[2][128][40];
    const int tid  = threadIdx.x;
    const int wid  = tid >> 5, lane = tid & 31;
    const int g    = lane >> 2, tg = lane & 3;
    const int bm   = blockIdx.y * 128, bn = blockIdx.x * 128;
    const int wm   = (wid & 3) * 32, wn = (wid >> 2) * 64;
    const int rowA = tid >> 2;
    const int kq   = (tid & 3) * 8;

    const int nk  = K >> 5;
    const int nch = TERMS * nk;

    float acc[2][8][4];
    #pragma unroll
    for (int mi=0;mi<2;mi++)
        #pragma unroll
        for (int ni=0;ni<8;ni++)
            #pragma unroll
            for (int q=0;q<4;q++) acc[mi][ni][q] = 0.f;

    uint4 a0v,a1v,b0v,b1v;
    auto ldchunk = [&](int c){
        int term = c / nk, kc = c - term*nk;
        const __nv_bfloat16* Ab = (term<2) ? Ahi : Alo;
        const __nv_bfloat16* Bb = (term==1) ? Blo : Bhi;
        const __nv_bfloat16* ap = Ab + (size_t)(bm+rowA)*K + kc*32 + kq;
        const __nv_bfloat16* bp = Bb + (size_t)(bn+rowA)*K + kc*32 + kq;
        a0v = *(const uint4*)ap;  a1v = *(const uint4*)(ap + (size_t)64*K);
        b0v = *(const uint4*)bp;  b1v = *(const uint4*)(bp + (size_t)64*K);
    };
    auto stchunk = [&](int buf){
        *(uint4*)&As[buf][rowA][kq]    = a0v;
        *(uint4*)&As[buf][rowA+64][kq] = a1v;
        *(uint4*)&Bs[buf][rowA][kq]    = b0v;
        *(uint4*)&Bs[buf][rowA+64][kq] = b1v;
    };

    ldchunk(0); stchunk(0);
    __syncthreads();

    for (int c=0; c<nch; c++){
        const int buf = c & 1;
        const bool has = (c+1 < nch);
        if (has) ldchunk(c+1);
        #pragma unroll
        for (int kk=0; kk<32; kk+=16){
            unsigned af[2][4];
            #pragma unroll
            for (int mi=0;mi<2;mi++){
                const int rb0 = wm + mi*16 + g;
                af[mi][0] = *(const unsigned*)&As[buf][rb0  ][kk + tg*2];
                af[mi][1] = *(const unsigned*)&As[buf][rb0+8][kk + tg*2];
                af[mi][2] = *(const unsigned*)&As[buf][rb0  ][kk + 8 + tg*2];
                af[mi][3] = *(const unsigned*)&As[buf][rb0+8][kk + 8 + tg*2];
            }
            #pragma unroll
            for (int ni=0;ni<8;ni++){
                const int nr = wn + ni*8 + g;
                unsigned bw0 = *(const unsigned*)&Bs[buf][nr][kk + tg*2];
                unsigned bw1 = *(const unsigned*)&Bs[buf][nr][kk + 8 + tg*2];
                mma16816(acc[0][ni], af[0], bw0, bw1);
                mma16816(acc[1][ni], af[1], bw0, bw1);
            }
        }
        if (has) stchunk(buf ^ 1);
        __syncthreads();
    }

    // epilogue
    #pragma unroll
    for (int mi=0;mi<2;mi++){
        const int ra = bm + wm + mi*16 + g;
        const int rb_ = ra + 8;
        float4 ca, cb;
        if (RBMODE == 2){
            ca = *(const float4*)(c4g + (size_t)ra*4);
            cb = *(const float4*)(c4g + (size_t)rb_*4);
        }
        float pa = 0.f, pb = 0.f;   // OMODE 3 partials
        #pragma unroll
        for (int ni=0;ni<8;ni++){
            const int col = bn + wn + ni*8 + tg*2;
            float2 bv = *(const float2*)&bias[col];
            float v00 = acc[mi][ni][0] + bv.x, v01 = acc[mi][ni][1] + bv.y;
            float v10 = acc[mi][ni][2] + bv.x, v11 = acc[mi][ni][3] + bv.y;
            if (RBMODE == 2){
                float2 r0 = *(const float2*)(iw1g + (size_t)768*256 + col);
                float2 r1 = *(const float2*)(iw1g + (size_t)769*256 + col);
                float2 r2 = *(const float2*)(iw1g + (size_t)770*256 + col);
                float2 r3 = *(const float2*)(iw1g + (size_t)771*256 + col);
                v00 += ca.x*r0.x + ca.y*r1.x + ca.z*r2.x + ca.w*r3.x;
                v01 += ca.x*r0.y + ca.y*r1.y + ca.z*r2.y + ca.w*r3.y;
                v10 += cb.x*r0.x + cb.y*r1.x + cb.z*r2.x + cb.w*r3.x;
                v11 += cb.x*r0.y + cb.y*r1.y + cb.z*r2.y + cb.w*r3.y;
            }
            if (RELU){
                v00=fmaxf(v00,0.f); v01=fmaxf(v01,0.f);
                v10=fmaxf(v10,0.f); v11=fmaxf(v11,0.f);
            }
            if (OMODE == 0){
                *(float2*)&Cf[(size_t)ra*ldc + col]  = make_float2(v00,v01);
                *(float2*)&Cf[(size_t)rb_*ldc + col] = make_float2(v10,v11);
            } else if (OMODE == 2){
                *(unsigned*)&Chi[(size_t)ra*ldc + col]  = packbf(v00,v01);
                *(unsigned*)&Chi[(size_t)rb_*ldc + col] = packbf(v10,v11);
            } else if (OMODE == 3){
                float2 w3v = *(const float2*)&iw3g[col];
                pa += v00*w3v.x + v01*w3v.y;
                pb += v10*w3v.x + v11*w3v.y;
            } else {
                float h00=__bfloat162float(__float2bfloat16(v00));
                float h01=__bfloat162float(__float2bfloat16(v01));
                float h10=__bfloat162float(__float2bfloat16(v10));
                float h11=__bfloat162float(__float2bfloat16(v11));
                *(unsigned*)&Chi[(size_t)ra*ldc + col]  = packbf(h00,h01);
                *(unsigned*)&Chi[(size_t)rb_*ldc + col] = packbf(h10,h11);
                *(unsigned*)&Clo[(size_t)ra*ldc + col]  = packbf(v00-h00, v01-h01);
                *(unsigned*)&Clo[(size_t)rb_*ldc + col] = packbf(v10-h10, v11-h11);
            }
        }
        if (OMODE == 3){
            // reduce across the 4-lane tg group (lanes 4g..4g+3)
            pa += __shfl_xor_sync(0xffffffffu, pa, 1);
            pa += __shfl_xor_sync(0xffffffffu, pa, 2);
            pb += __shfl_xor_sync(0xffffffffu, pb, 1);
            pb += __shfl_xor_sync(0xffffffffu, pb, 2);
            if (tg == 0){
                atomicAdd(&Cf[ra], pa);
                atomicAdd(&Cf[rb_], pb);
            }
        }
    }
}

// ---------------- LayerNorm over rows of 256 ---------------------------------
// LMODE: 0 fp32 out, 2 bf16 hi-only out
template<int LMODE>
__global__ void ln_kernel(const float* __restrict__ z, const float* __restrict__ gg,
                          const float* __restrict__ bb,
                          __nv_bfloat16* __restrict__ oh, float* __restrict__ of)
{
    int row  = blockIdx.x*8 + (threadIdx.x>>5);
    int lane = threadIdx.x & 31;
    const float* rr = z + (size_t)row*256 + lane*8;
    float v[8];
    float4 p0 = *(const float4*)rr;
    float4 p1 = *(const float4*)(rr+4);
    v[0]=p0.x;v[1]=p0.y;v[2]=p0.z;v[3]=p0.w;v[4]=p1.x;v[5]=p1.y;v[6]=p1.z;v[7]=p1.w;
    float s=0.f;
    #pragma unroll
    for (int j=0;j<8;j++) s+=v[j];
    #pragma unroll
    for (int off=16;off>0;off>>=1) s += __shfl_xor_sync(0xffffffffu, s, off);
    float mu = s * (1.f/256.f);
    float q=0.f;
    #pragma unroll
    for (int j=0;j<8;j++){ float d=v[j]-mu; q+=d*d; }
    #pragma unroll
    for (int off=16;off>0;off>>=1) q += __shfl_xor_sync(0xffffffffu, q, off);
    float inv = rsqrtf(q*(1.f/256.f) + 1e-5f);
    size_t off = (size_t)row*256 + lane*8;
    if (LMODE == 2){
        float h[8];
        #pragma unroll
        for (int j=0;j<8;j++)
            h[j] = (v[j]-mu)*inv*gg[lane*8+j] + bb[lane*8+j];
        *(uint4*)(oh+off) = make_uint4(packbf(h[0],h[1]),packbf(h[2],h[3]),packbf(h[4],h[5]),packbf(h[6],h[7]));
    } else {
        #pragma unroll
        for (int j=0;j<8;j++)
            of[off+j] = (v[j]-mu)*inv*gg[lane*8+j] + bb[lane*8+j];
    }
}

// ---------------- importance scalar (candidates only) -------------------------
__global__ void imp_kernel(const float* __restrict__ z, const float* __restrict__ iw3,
                           const float* __restrict__ ib3, float* __restrict__ imp)
{
    int row  = blockIdx.x*8 + (threadIdx.x>>5);
    int lane = threadIdx.x & 31;
    const float* r = z + (size_t)row*256 + lane*8;
    float s = 0.f;
    #pragma unroll
    for (int j=0;j<8;j++) s += r[j]*iw3[lane*8+j];
    #pragma unroll
    for (int off=16;off>0;off>>=1) s += __shfl_xor_sync(0xffffffffu, s, off);
    if (lane==0) imp[row] = s + ib3[0];
}

// ---------------- per-batch top-256 candidates (approx keys) ------------------
__global__ void topk256_kernel(const float* __restrict__ imp, const float* __restrict__ noise,
                               int* __restrict__ cand)
{
    extern __shared__ unsigned skey[];
    __shared__ unsigned hist[256];
    __shared__ unsigned s_prefix, s_mask;
    __shared__ int s_rem, s_cnt, s_eqcnt;
    __shared__ int eqbuf[512];
    const int b = blockIdx.x;
    const int tid = threadIdx.x;
    for (int i=tid;i<PB;i+=1024)
        skey[i] = f2u(imp[b*PB+i] + noise[b*PB+i]);
    if (tid==0){ s_prefix=0u; s_mask=0u; s_rem=KSEL; }
    __syncthreads();
    for (int round=0; round<4; round++){
        const int shift = 24 - 8*round;
        if (tid<256) hist[tid]=0u;
        __syncthreads();
        unsigned mask = s_mask, prefix = s_prefix;
        for (int i=tid;i<PB;i+=1024){
            unsigned k = skey[i];
            if ((k & mask) == prefix) atomicAdd(&hist[(k>>shift)&255u], 1u);
        }
        __syncthreads();
        if (tid==0){
            int rem = s_rem; unsigned cum=0; int bsel=0;
            for (int bin=255; bin>=0; bin--){
                if (cum + hist[bin] >= (unsigned)rem){ bsel=bin; break; }
                cum += hist[bin];
            }
            s_rem    = rem - (int)cum;
            s_prefix = prefix | ((unsigned)bsel << shift);
            s_mask   = mask   | (0xFFu << shift);
        }
        __syncthreads();
    }
    const unsigned kth = s_prefix;
    const int rEq = s_rem;
    if (tid==0){ s_cnt=0; s_eqcnt=0; }
    __syncthreads();
    for (int i=tid;i<PB;i+=1024){
        unsigned k = skey[i];
        if (k > kth){
            int p = atomicAdd(&s_cnt,1);
            cand[b*KSEL+p] = i;
        } else if (k == kth){
            int p = atomicAdd(&s_eqcnt,1);
            if (p < 512) eqbuf[p] = i;
        }
    }
    __syncthreads();
    if (tid==0){
        int base = s_cnt;
        for (int a=0;a<rEq;a++) cand[b*KSEL+base+a] = eqbuf[a];
    }
}

// ---------------- gather candidate inputs + compute rbc -----------------------
__global__ void cand_gather(const int* __restrict__ cand, const float* __restrict__ iw1,
                            float* __restrict__ xc, float* __restrict__ rbc)
{
    const int j = blockIdx.x;
    const int b = j >> 8;
    const int i = cand[j];
    const int gidx = b*PB + i;
    const int t = threadIdx.x;            // 64
    if (t < 2) ((float4*)xc)[j*2+t] = ((const float4*)g_x8)[(size_t)gidx*2+t];
    const int n = t*4;
    float4 c  = *(const float4*)(g_c4 + (size_t)gidx*4);
    float4 r0 = *(const float4*)(iw1 + (size_t)768*256 + n);
    float4 r1 = *(const float4*)(iw1 + (size_t)769*256 + n);
    float4 r2 = *(const float4*)(iw1 + (size_t)770*256 + n);
    float4 r3 = *(const float4*)(iw1 + (size_t)771*256 + n);
    float4 o;
    o.x = c.x*r0.x + c.y*r1.x + c.z*r2.x + c.w*r3.x;
    o.y = c.x*r0.y + c.y*r1.y + c.z*r2.y + c.w*r3.y;
    o.z = c.x*r0.z + c.y*r1.z + c.z*r2.z + c.w*r3.z;
    o.w = c.x*r0.w + c.y*r1.w + c.z*r2.w + c.w*r3.w;
    *(float4*)(rbc + (size_t)j*256 + n) = o;
}

// ---------------- exact top-128 among candidates ------------------------------
__global__ void topk_final(const float* __restrict__ impc, const float* __restrict__ noise,
                           const int* __restrict__ cand, const float* __restrict__ c4,
                           float* __restrict__ cent)
{
    __shared__ unsigned long long s[KSEL];
    const int b = blockIdx.x, t = threadIdx.x;
    const int i = cand[b*KSEL+t];
    float v = impc[b*KSEL+t] + noise[b*PB+i];
    s[t] = ((unsigned long long)(~f2u(v)) << 32) | (unsigned)i;
    __syncthreads();
    for (int ksz=2; ksz<=KSEL; ksz<<=1){
        for (int j=ksz>>1; j>0; j>>=1){
            int ixj = t ^ j;
            if (ixj > t){
                unsigned long long a = s[t], c = s[ixj];
                bool up = ((t & ksz) == 0);
                if (up ? (a > c) : (a < c)){ s[t]=c; s[ixj]=a; }
            }
            __syncthreads();
        }
    }
    if (t < MTOK){
        int i2 = (unsigned)(s[t] & 0xffffffffu);
        #pragma unroll
        for (int q=0;q<4;q++) cent[(b*MTOK+t)*4+q] = c4[(size_t)(b*PB+i2)*4+q];
    }
}

// ---------------- stable sort of 128 cents by t -------------------------------
__global__ void sortt_kernel(const float* __restrict__ cent, int* __restrict__ order)
{
    __shared__ unsigned long long s[128];
    const int b = blockIdx.x, tid = threadIdx.x;
    float t = cent[(b*MTOK+tid)*4+3];
    s[tid] = ((unsigned long long)f2u(t) << 32) | (unsigned)tid;
    __syncthreads();
    for (int ksz=2; ksz<=128; ksz<<=1){
        for (int j=ksz>>1; j>0; j>>=1){
            int ixj = tid ^ j;
            if (ixj > tid){
                unsigned long long a = s[tid], c = s[ixj];
                bool up = ((tid & ksz) == 0);
                if (up ? (a > c) : (a < c)){ s[tid]=c; s[ixj]=a; }
            }
            __syncthreads();
        }
    }
    order[b*MTOK+tid] = (int)(s[tid] & 0xffffffffu);
}

// ---------------- brute-force 16-NN -------------------------------------------
__global__ void knn_kernel(const float* __restrict__ c4, const float* __restrict__ cent,
                           int* __restrict__ knn)
{
    __shared__ unsigned long long lists[128][KNN];
    const int bm = blockIdx.x;
    const int b  = bm >> 7;
    const int tid = threadIdx.x;
    const float cx = cent[bm*4+0], cy = cent[bm*4+1], cz = cent[bm*4+2], ct = cent[bm*4+3];
    unsigned long long loc[KNN];
    #pragma unroll
    for (int q=0;q<KNN;q++) loc[q] = ~0ull;
    const float* cb = c4 + (size_t)b*PB*4;
    for (int i=tid;i<PB;i+=128){
        float4 p = *(const float4*)(cb + (size_t)i*4);
        float dx=p.x-cx, dy=p.y-cy, dz=p.z-cz, dt=p.w-ct;
        float d2 = dx*dx + dy*dy + dz*dz + dt*dt;
        unsigned long long key = ((unsigned long long)(__float_as_uint(d2)|0x80000000u) << 32) | (unsigned)i;
        if (key < loc[KNN-1]){
            loc[KNN-1] = key;
            #pragma unroll
            for (int q=KNN-1;q>0;q--){
                if (loc[q] < loc[q-1]){ unsigned long long t=loc[q]; loc[q]=loc[q-1]; loc[q-1]=t; }
            }
        }
    }
    #pragma unroll
    for (int q=0;q<KNN;q++) lists[tid][q]=loc[q];
    __syncthreads();
    for (int sgap=64; sgap>0; sgap>>=1){
        if (tid < sgap){
            unsigned long long out[KNN];
            int i1=0, i2=0;
            #pragma unroll
            for (int q=0;q<KNN;q++){
                unsigned long long a=lists[tid][i1], c=lists[tid+sgap][i2];
                if (a<=c){ out[q]=a; i1++; } else { out[q]=c; i2++; }
            }
            #pragma unroll
            for (int q=0;q<KNN;q++) lists[tid][q]=out[q];
        }
        __syncthreads();
    }
    if (tid < KNN) knn[bm*KNN+tid] = (int)(lists[0][tid] & 0xffffffffu);
}

// ---------------- gather x8 rows of knn neighbors -----------------------------
__global__ void gatherx_kernel(const int* __restrict__ knn, float* __restrict__ gx)
{
    const int r = blockIdx.x*256 + threadIdx.x;   // 0..NGATH-1
    const int bm = r / KNN;
    const int b  = bm >> 7;
    const int nb = b*PB + knn[r];
    ((float4*)gx)[(size_t)r*2+0] = ((const float4*)g_x8)[(size_t)nb*2+0];
    ((float4*)gx)[(size_t)r*2+1] = ((const float4*)g_x8)[(size_t)nb*2+1];
}

// ---------------- max pool over groups of 16 ----------------------------------
__global__ void pool_kernel(const float* __restrict__ pfg, float* __restrict__ pooled)
{
    const int bm = blockIdx.x;
    const int tid = threadIdx.x;
    for (int c=tid;c<TOKD;c+=256){
        float m = -3.402823466e38f;
        #pragma unroll
        for (int q=0;q<KNN;q++)
            m = fmaxf(m, pfg[(size_t)(bm*KNN+q)*768 + c]);
        pooled[(size_t)bm*TOKD + c] = m;
    }
}

// ---------------- scatter to output in time order -----------------------------
__global__ void out_kernel(const float* __restrict__ tok, const float* __restrict__ cent,
                           const int* __restrict__ order, float* __restrict__ out)
{
    const int bj = blockIdx.x;
    const int b  = bj >> 7;
    const int o  = order[bj];
    const float* src = tok + (size_t)(b*MTOK+o)*TOKD;
    float* dst = out + (size_t)bj*TOKD;
    for (int c=threadIdx.x;c<TOKD;c+=256) dst[c]=src[c];
    if (threadIdx.x < 4) out[(size_t)BATCH*MTOK*TOKD + bj*4 + threadIdx.x] = cent[(b*MTOK+o)*4+threadIdx.x];
    if (threadIdx.x == 4) out[(size_t)BATCH*MTOK*TOKD + (size_t)BATCH*MTOK*4 + bj] = 1.0f;
}

// ---------------- launch ------------------------------------------------------
extern "C" void kernel_launch(void* const* d_in, const int* in_sizes, int n_in,
                              void* d_out, int out_size)
{
    (void)in_sizes; (void)n_in; (void)out_size;
    const float* coords = (const float*)d_in[0];
    const float* feats  = (const float*)d_in[1];
    const float* w1  = (const float*)d_in[3];  const float* b1  = (const float*)d_in[4];
    const float* w2  = (const float*)d_in[5];  const float* b2  = (const float*)d_in[6];
    const float* w3  = (const float*)d_in[7];  const float* b3  = (const float*)d_in[8];
    const float* w4  = (const float*)d_in[9];  const float* b4  = (const float*)d_in[10];
    const float* iw1 = (const float*)d_in[11]; const float* ib1 = (const float*)d_in[12];
    const float* lng = (const float*)d_in[13]; const float* lnb = (const float*)d_in[14];
    const float* iw2 = (const float*)d_in[15]; const float* ib2 = (const float*)d_in[16];
    const float* iw3 = (const float*)d_in[17]; const float* ib3 = (const float*)d_in[18];
    const float* nw1 = (const float*)d_in[19]; const float* nb1 = (const float*)d_in[20];
    const float* nw2 = (const float*)d_in[21]; const float* nb2 = (const float*)d_in[22];
    const float* noise = (const float*)d_in[23];

    void *px8,*pw1p,*pc4,*ph1h,*ph2h,*ph3h,*pwp,*pbp,*pz0;
    void *pz1,*pz2h,*pimp,*pcand,*pxc,*prbc,*ph1c,*ph2c,*ph3c,*pz1c,*pz2c,*pz3c,*pimpc;
    void *pcent,*pord,*pknn,*pgx,*ph1gh,*ph1gl,*ph2gh,*ph2gl,*pgh,*pgl,*ppfg,*ppool,*pt1,*ptok;
    void *pw2h,*pw2l,*pw3h,*pw3l,*pw4h,*pw4l,*pwph,*pwpl,*piw2h,*piw2l;
    cudaGetSymbolAddress(&px8,g_x8);     cudaGetSymbolAddress(&pw1p,g_w1p);
    cudaGetSymbolAddress(&pc4,g_c4);
    cudaGetSymbolAddress(&ph1h,g_h1h);
    cudaGetSymbolAddress(&ph2h,g_h2h);   cudaGetSymbolAddress(&ph3h,g_h3h);
    cudaGetSymbolAddress(&pwp,g_wp);     cudaGetSymbolAddress(&pbp,g_biasp);
    cudaGetSymbolAddress(&pz0,g_zero256);
    cudaGetSymbolAddress(&pz1,g_z1);     cudaGetSymbolAddress(&pz2h,g_z2h);
    cudaGetSymbolAddress(&pimp,g_imp);   cudaGetSymbolAddress(&pcand,g_cand);
    cudaGetSymbolAddress(&pxc,g_xc);     cudaGetSymbolAddress(&prbc,g_rbc);
    cudaGetSymbolAddress(&ph1c,g_h1c);   cudaGetSymbolAddress(&ph2c,g_h2c);
    cudaGetSymbolAddress(&ph3c,g_h3c);   cudaGetSymbolAddress(&pz1c,g_z1c);
    cudaGetSymbolAddress(&pz2c,g_z2c);   cudaGetSymbolAddress(&pz3c,g_z3c);
    cudaGetSymbolAddress(&pimpc,g_impc);
    cudaGetSymbolAddress(&pcent,g_cent); cudaGetSymbolAddress(&pord,g_order);
    cudaGetSymbolAddress(&pknn,g_knn);   cudaGetSymbolAddress(&pgx,g_gx);
    cudaGetSymbolAddress(&ph1gh,g_h1gh); cudaGetSymbolAddress(&ph1gl,g_h1gl);
    cudaGetSymbolAddress(&ph2gh,g_h2gh); cudaGetSymbolAddress(&ph2gl,g_h2gl);
    cudaGetSymbolAddress(&pgh,g_gh);     cudaGetSymbolAddress(&pgl,g_gl);
    cudaGetSymbolAddress(&ppfg,g_pfg);   cudaGetSymbolAddress(&ppool,g_pooled);
    cudaGetSymbolAddress(&pt1,g_t1);     cudaGetSymbolAddress(&ptok,g_tok);
    cudaGetSymbolAddress(&pw2h,g_w2th);  cudaGetSymbolAddress(&pw2l,g_w2tl);
    cudaGetSymbolAddress(&pw3h,g_w3th);  cudaGetSymbolAddress(&pw3l,g_w3tl);
    cudaGetSymbolAddress(&pw4h,g_w4th);  cudaGetSymbolAddress(&pw4l,g_w4tl);
    cudaGetSymbolAddress(&pwph,g_wpth);  cudaGetSymbolAddress(&pwpl,g_wptl);
    cudaGetSymbolAddress(&piw2h,g_iw2th);cudaGetSymbolAddress(&piw2l,g_iw2tl);

    cudaFuncSetAttribute(topk256_kernel, cudaFuncAttributeMaxDynamicSharedMemorySize, PB*4);

    prep_points<<<NPTS/256, 256>>>(coords, feats);
    prep_w<<<8, 256>>>(w1);
    biasp_init<<<1,256>>>(ib1, (float*)pbp);
    biasp_acc<<<8,256>>>(b4, iw1, (float*)pbp);
    init_imp<<<NPTS/256,256>>>(ib3, (float*)pimp);
    sgemm128<false,false,0><<<dim3(2,6),256>>>(w4, 768, iw1, 256, (const float*)pz0,
        nullptr, (float*)pwp, nullptr, nullptr, 256, 768);
    conv_wt<<<(512*256+255)/256,256>>>(w2, 256, 512, (__nv_bfloat16*)pw2h, (__nv_bfloat16*)pw2l);
    conv_wt<<<(768*512+255)/256,256>>>(w3, 512, 768, (__nv_bfloat16*)pw3h, (__nv_bfloat16*)pw3l);
    conv_wt<<<(768*768+255)/256,256>>>(w4, 768, 768, (__nv_bfloat16*)pw4h, (__nv_bfloat16*)pw4l);
    conv_wt<<<(256*768+255)/256,256>>>((const float*)pwp, 768, 256, (__nv_bfloat16*)pwph, (__nv_bfloat16*)pwpl);
    conv_wt<<<(256*256+255)/256,256>>>(iw2, 256, 256, (__nv_bfloat16*)piw2h, (__nv_bfloat16*)piw2l);

    // L1 scalar -> h1 hi-only (full points; 1-term trunk never reads lo)
    sgemm128<true,false,2><<<dim3(2,1024),256>>>((const float*)px8, 8, (const float*)pw1p, 256, b1,
        nullptr, nullptr, (__nv_bfloat16*)ph1h, nullptr, 256, 8);
    // trunk 1-term (importance-only precision), bf16-hi outputs
    hgemm<true,0,2,1><<<dim3(4,1024),256>>>((const __nv_bfloat16*)ph1h, nullptr,
        (const __nv_bfloat16*)pw2h,(const __nv_bfloat16*)pw2l, b2, nullptr, nullptr, nullptr,
        (__nv_bfloat16*)ph2h, nullptr, nullptr, 512, 256);
    hgemm<true,0,2,1><<<dim3(6,1024),256>>>((const __nv_bfloat16*)ph2h, nullptr,
        (const __nv_bfloat16*)pw3h,(const __nv_bfloat16*)pw3l, b3, nullptr, nullptr, nullptr,
        (__nv_bfloat16*)ph3h, nullptr, nullptr, 768, 512);
    // importance branch (1-term) with epilogue-generated rowbias
    hgemm<true,2,0,1><<<dim3(2,1024),256>>>((const __nv_bfloat16*)ph3h, nullptr,
        (const __nv_bfloat16*)pwph,(const __nv_bfloat16*)pwpl, (const float*)pbp,
        (const float*)pc4, iw1, nullptr,
        nullptr, nullptr, (float*)pz1, 256, 768);
    ln_kernel<2><<<NPTS/8,256>>>((const float*)pz1, lng, lnb, (__nv_bfloat16*)pz2h, nullptr);
    // iw2 GEMM with fused importance reduce (z3 never materialized)
    hgemm<true,0,3,1><<<dim3(2,1024),256>>>((const __nv_bfloat16*)pz2h, nullptr,
        (const __nv_bfloat16*)piw2h,(const __nv_bfloat16*)piw2l, ib2, nullptr, nullptr, iw3,
        nullptr, nullptr, (float*)pimp, 256, 256);

    // approx top-256 candidates, then exact scalar refinement
    topk256_kernel<<<BATCH,1024,PB*4>>>((const float*)pimp, noise, (int*)pcand);
    cand_gather<<<NCAND,64>>>((const int*)pcand, iw1, (float*)pxc, (float*)prbc);
    sgemm128<true,false,0><<<dim3(2,16),256>>>((const float*)pxc, 8, (const float*)pw1p, 256, b1,
        nullptr, (float*)ph1c, nullptr, nullptr, 256, 8);
    sgemm128<true,false,0><<<dim3(4,16),256>>>((const float*)ph1c, 256, w2, 512, b2,
        nullptr, (float*)ph2c, nullptr, nullptr, 512, 256);
    sgemm128<true,false,0><<<dim3(6,16),256>>>((const float*)ph2c, 512, w3, 768, b3,
        nullptr, (float*)ph3c, nullptr, nullptr, 768, 512);
    sgemm128<true,true,0><<<dim3(2,16),256>>>((const float*)ph3c, 768, (const float*)pwp, 256,
        (const float*)pbp, (const float*)prbc, (float*)pz1c, nullptr, nullptr, 256, 768);
    ln_kernel<0><<<NCAND/8,256>>>((const float*)pz1c, lng, lnb, nullptr, (float*)pz2c);
    sgemm128<true,false,0><<<dim3(2,16),256>>>((const float*)pz2c, 256, iw2, 256, ib2,
        nullptr, (float*)pz3c, nullptr, nullptr, 256, 256);
    imp_kernel<<<NCAND/8,256>>>((const float*)pz3c, iw3, ib3, (float*)pimpc);
    topk_final<<<BATCH,KSEL>>>((const float*)pimpc, noise, (const int*)pcand,
                               (const float*)pc4, (float*)pcent);

    // neighborhoods (coordinates only)
    sortt_kernel<<<BATCH,128>>>((const float*)pcent, (int*)pord);
    knn_kernel<<<BATCH*MTOK,128>>>((const float*)pc4, (const float*)pcent, (int*)pknn);

    // neighbor trunk recompute at full (3-term) precision: 16384 rows
    gatherx_kernel<<<NGATH/256,256>>>((const int*)pknn, (float*)pgx);
    sgemm128<true,false,1><<<dim3(2,NGATH/128),256>>>((const float*)pgx, 8, (const float*)pw1p, 256, b1,
        nullptr, nullptr, (__nv_bfloat16*)ph1gh, (__nv_bfloat16*)ph1gl, 256, 8);
    hgemm<true,0,1,3><<<dim3(4,NGATH/128),256>>>((const __nv_bfloat16*)ph1gh,(const __nv_bfloat16*)ph1gl,
        (const __nv_bfloat16*)pw2h,(const __nv_bfloat16*)pw2l, b2, nullptr, nullptr, nullptr,
        (__nv_bfloat16*)ph2gh,(__nv_bfloat16*)ph2gl, nullptr, 512, 256);
    hgemm<true,0,1,3><<<dim3(6,NGATH/128),256>>>((const __nv_bfloat16*)ph2gh,(const __nv_bfloat16*)ph2gl,
        (const __nv_bfloat16*)pw3h,(const __nv_bfloat16*)pw3l, b3, nullptr, nullptr, nullptr,
        (__nv_bfloat16*)pgh,(__nv_bfloat16*)pgl, nullptr, 768, 512);
    hgemm<false,0,0,3><<<dim3(6,NGATH/128),256>>>((const __nv_bfloat16*)pgh,(const __nv_bfloat16*)pgl,
        (const __nv_bfloat16*)pw4h,(const __nv_bfloat16*)pw4l, b4, nullptr, nullptr, nullptr,
        nullptr, nullptr, (float*)ppfg, 768, 768);
    pool_kernel<<<BATCH*MTOK,256>>>((const float*)ppfg, (float*)ppool);

    // token MLP scalar fp32
    sgemm128<true ,false,0><<<dim3(6,8),256>>>((const float*)ppool, 768, nw1, 768, nb1,
        nullptr, (float*)pt1, nullptr, nullptr, 768, 768);
    sgemm128<false,false,0><<<dim3(6,8),256>>>((const float*)pt1, 768, nw2, 768, nb2,
        nullptr, (float*)ptok, nullptr, nullptr, 768, 768);

    out_kernel<<<BATCH*MTOK,256>>>((const float*)ptok, (const float*)pcent, (const int*)pord, (float*)d_out);
}

// round 17
// speedup vs baseline: 1.0868x; 1.0119x over previous
#include <cuda_runtime.h>
#include <cuda_bf16.h>
#include <math.h>
#include <stdint.h>

#define NPTS   131072
#define PB     16384
#define BATCH  8
#define MTOK   128
#define KNN    16
#define TOKD   768
#define NGATH  (BATCH*MTOK*KNN)   // 16384 gathered neighbor rows
#define KSEL   256                // candidate pool per batch
#define NCAND  (BATCH*KSEL)       // 2048

// ---------------- scratch (device globals; no allocs allowed) ----------------
__device__ __align__(16) float g_x8[NPTS*8];
__device__ __align__(16) float g_w1p[8*256];
__device__ __align__(16) float g_c4[NPTS*4];
__device__ __align__(16) __nv_bfloat16 g_h1h[(size_t)NPTS*256];
__device__ __align__(16) __nv_bfloat16 g_h2h[(size_t)NPTS*512];
__device__ __align__(16) __nv_bfloat16 g_h3h[(size_t)NPTS*768];
__device__ __align__(16) float g_wp[768*256];          // w4 @ iw1[0:768]
__device__ __align__(16) float g_biasp[256];
__device__ __align__(16) float g_zero256[256];         // stays zero
__device__ __align__(16) __nv_bfloat16 g_z1h[(size_t)NPTS*256];
__device__ __align__(16) __nv_bfloat16 g_z2h[(size_t)NPTS*256];
__device__ float g_imp[NPTS];
// split weights [N][K] bf16 hi/lo
__device__ __align__(16) __nv_bfloat16 g_w2th[512*256],  g_w2tl[512*256];
__device__ __align__(16) __nv_bfloat16 g_w3th[768*512],  g_w3tl[768*512];
__device__ __align__(16) __nv_bfloat16 g_w4th[768*768],  g_w4tl[768*768];
__device__ __align__(16) __nv_bfloat16 g_wpth[256*768],  g_wptl[256*768];
__device__ __align__(16) __nv_bfloat16 g_iw2th[256*256], g_iw2tl[256*256];
// refinement
__device__ int   g_cand[NCAND];
__device__ __align__(16) float g_xc[NCAND*8];
__device__ __align__(16) float g_rbc[NCAND*256];
__device__ __align__(16) float g_h1c[NCAND*256];
__device__ __align__(16) float g_h2c[NCAND*512];
__device__ __align__(16) float g_h3c[NCAND*768];
__device__ __align__(16) float g_z1c[NCAND*256];
__device__ __align__(16) float g_z2c[NCAND*256];
__device__ __align__(16) float g_z3c[NCAND*256];
__device__ float g_impc[NCAND];
// selection + neighbor recompute
__device__ float g_cent[BATCH*MTOK*4];
__device__ int   g_order[BATCH*MTOK];
__device__ int   g_knn[BATCH*MTOK*KNN];
__device__ __align__(16) float g_gx[NGATH*8];
__device__ __align__(16) __nv_bfloat16 g_h1gh[(size_t)NGATH*256], g_h1gl[(size_t)NGATH*256];
__device__ __align__(16) __nv_bfloat16 g_h2gh[(size_t)NGATH*512], g_h2gl[(size_t)NGATH*512];
__device__ __align__(16) __nv_bfloat16 g_gh[(size_t)NGATH*768], g_gl[(size_t)NGATH*768];
__device__ __align__(16) float g_pooled[BATCH*MTOK*TOKD];
__device__ __align__(16) float g_t1[BATCH*MTOK*TOKD];
__device__ __align__(16) float g_tok[BATCH*MTOK*TOKD];

__device__ __forceinline__ unsigned packbf(float lo, float hi){
    unsigned r; asm("cvt.rn.bf16x2.f32 %0, %2, %1;" : "=r"(r) : "f"(lo), "f"(hi)); return r;
}
__device__ __forceinline__ unsigned f2u(float x){
    unsigned u = __float_as_uint(x);
    return (u & 0x80000000u) ? ~u : (u | 0x80000000u);
}

// ---------------- prep -------------------------------------------------------
__global__ void prep_points(const float* __restrict__ coords,
                            const float* __restrict__ feats)
{
    int i = blockIdx.x*blockDim.x + threadIdx.x;
    if (i >= NPTS) return;
    #pragma unroll
    for (int j=0;j<6;j++) g_x8[i*8+j] = feats[i*6+j];
    g_x8[i*8+6]=0.f; g_x8[i*8+7]=0.f;
    #pragma unroll
    for (int j=0;j<4;j++) g_c4[i*4+j] = coords[i*5+1+j];
}
__global__ void prep_w(const float* __restrict__ w1)
{
    int idx = blockIdx.x*blockDim.x + threadIdx.x;
    if (idx < 8*256) g_w1p[idx] = (idx < 6*256) ? w1[idx] : 0.f;
}
__global__ void biasp_init(const float* __restrict__ ib1, float* __restrict__ bp)
{ bp[threadIdx.x] = ib1[threadIdx.x]; }
__global__ void biasp_acc(const float* __restrict__ b4, const float* __restrict__ iw1,
                          float* __restrict__ bp)
{
    int n = threadIdx.x;
    int j0 = blockIdx.x*96;
    float s = 0.f;
    for (int j=j0;j<j0+96;j++) s += b4[j]*iw1[(size_t)j*256+n];
    atomicAdd(&bp[n], s);
}
__global__ void init_imp(const float* __restrict__ ib3, float* __restrict__ imp)
{
    int i = blockIdx.x*blockDim.x + threadIdx.x;
    if (i < NPTS) imp[i] = ib3[0];
}
__global__ void conv_wt(const float* __restrict__ src, int K, int N,
                        __nv_bfloat16* __restrict__ dh, __nv_bfloat16* __restrict__ dl)
{
    int idx = blockIdx.x*blockDim.x + threadIdx.x;
    if (idx >= N*K) return;
    int n = idx / K, k = idx - n*K;
    float v = src[(size_t)k*N + n];
    __nv_bfloat16 h = __float2bfloat16(v);
    dh[idx] = h;
    dl[idx] = __float2bfloat16(v - __bfloat162float(h));
}

// ---------------- scalar SGEMM (proven core) ---------------------------------
// OM: 0 fp32 out, 1 bf16 hi/lo split out, 2 bf16 hi-only out
template<bool RELU, bool RB, int OM>
__global__ __launch_bounds__(256,2) void sgemm128(
    const float* __restrict__ A, int lda,
    const float* __restrict__ B, int N,
    const float* __restrict__ bias,
    const float* __restrict__ rowbias,
    float* __restrict__ C,
    __nv_bfloat16* __restrict__ Chi, __nv_bfloat16* __restrict__ Clo,
    int ldc, int K)
{
    __shared__ float As[2][8][128];
    __shared__ float Bs[2][8][128];
    const int tid  = threadIdx.x;
    const int bm   = blockIdx.y * 128;
    const int bn   = blockIdx.x * 128;
    const int arow = tid >> 1;
    const int acol = (tid & 1) * 4;
    const int brow = tid >> 5;
    const int bcol = (tid & 31) * 4;
    const int tx   = tid & 15;
    const int ty   = tid >> 4;

    const float* Aptr = A + (size_t)(bm + arow) * lda + acol;
    const float* Bptr = B + (size_t)brow * N + bn + bcol;

    float acc[8][8];
    #pragma unroll
    for (int i=0;i<8;i++)
        #pragma unroll
        for (int j=0;j<8;j++) acc[i][j]=0.f;

    {
        float4 a = *(const float4*)Aptr;
        As[0][acol+0][arow]=a.x; As[0][acol+1][arow]=a.y;
        As[0][acol+2][arow]=a.z; As[0][acol+3][arow]=a.w;
        *(float4*)&Bs[0][brow][bcol] = *(const float4*)Bptr;
    }
    __syncthreads();

    const int ktiles = K >> 3;
    int buf = 0;
    for (int kt=0; kt<ktiles; kt++){
        float4 a, bv;
        const bool has = (kt+1 < ktiles);
        if (has){
            a  = *(const float4*)(Aptr + (kt+1)*8);
            bv = *(const float4*)(Bptr + (size_t)(kt+1)*8*N);
        }
        #pragma unroll
        for (int k=0;k<8;k++){
            float4 a0 = *(const float4*)&As[buf][k][ty*4];
            float4 a1 = *(const float4*)&As[buf][k][64+ty*4];
            float4 b0 = *(const float4*)&Bs[buf][k][tx*4];
            float4 b1 = *(const float4*)&Bs[buf][k][64+tx*4];
            float ar[8] = {a0.x,a0.y,a0.z,a0.w,a1.x,a1.y,a1.z,a1.w};
            float br[8] = {b0.x,b0.y,b0.z,b0.w,b1.x,b1.y,b1.z,b1.w};
            #pragma unroll
            for (int i=0;i<8;i++)
                #pragma unroll
                for (int j=0;j<8;j++)
                    acc[i][j] += ar[i]*br[j];
        }
        if (has){
            const int nb = buf^1;
            As[nb][acol+0][arow]=a.x; As[nb][acol+1][arow]=a.y;
            As[nb][acol+2][arow]=a.z; As[nb][acol+3][arow]=a.w;
            *(float4*)&Bs[nb][brow][bcol] = bv;
        }
        __syncthreads();
        buf ^= 1;
    }

    float4 bv0 = *(const float4*)(bias + bn + tx*4);
    float4 bv1 = *(const float4*)(bias + bn + 64 + tx*4);
    #pragma unroll
    for (int i=0;i<8;i++){
        const int row = bm + ((i<4) ? (ty*4+i) : (64 + ty*4 + i - 4));
        float4 o0, o1;
        o0.x=acc[i][0]+bv0.x; o0.y=acc[i][1]+bv0.y; o0.z=acc[i][2]+bv0.z; o0.w=acc[i][3]+bv0.w;
        o1.x=acc[i][4]+bv1.x; o1.y=acc[i][5]+bv1.y; o1.z=acc[i][6]+bv1.z; o1.w=acc[i][7]+bv1.w;
        if (RB){
            float4 r0 = *(const float4*)(rowbias + (size_t)row*ldc + bn + tx*4);
            float4 r1 = *(const float4*)(rowbias + (size_t)row*ldc + bn + 64 + tx*4);
            o0.x+=r0.x; o0.y+=r0.y; o0.z+=r0.z; o0.w+=r0.w;
            o1.x+=r1.x; o1.y+=r1.y; o1.z+=r1.z; o1.w+=r1.w;
        }
        if (RELU){
            o0.x=fmaxf(o0.x,0.f); o0.y=fmaxf(o0.y,0.f); o0.z=fmaxf(o0.z,0.f); o0.w=fmaxf(o0.w,0.f);
            o1.x=fmaxf(o1.x,0.f); o1.y=fmaxf(o1.y,0.f); o1.z=fmaxf(o1.z,0.f); o1.w=fmaxf(o1.w,0.f);
        }
        if (OM == 0){
            *(float4*)(C + (size_t)row*ldc + bn + tx*4)      = o0;
            *(float4*)(C + (size_t)row*ldc + bn + 64 + tx*4) = o1;
        } else if (OM == 2){
            *(uint2*)(Chi + (size_t)row*ldc + bn + tx*4)      = make_uint2(packbf(o0.x,o0.y), packbf(o0.z,o0.w));
            *(uint2*)(Chi + (size_t)row*ldc + bn + 64 + tx*4) = make_uint2(packbf(o1.x,o1.y), packbf(o1.z,o1.w));
        } else {
            float v[8] = {o0.x,o0.y,o0.z,o0.w,o1.x,o1.y,o1.z,o1.w};
            float h[8], l[8];
            #pragma unroll
            for (int q=0;q<8;q++){
                __nv_bfloat16 hb = __float2bfloat16(v[q]);
                h[q] = __bfloat162float(hb); l[q] = v[q]-h[q];
            }
            *(uint2*)(Chi + (size_t)row*ldc + bn + tx*4)      = make_uint2(packbf(h[0],h[1]), packbf(h[2],h[3]));
            *(uint2*)(Chi + (size_t)row*ldc + bn + 64 + tx*4) = make_uint2(packbf(h[4],h[5]), packbf(h[6],h[7]));
            *(uint2*)(Clo + (size_t)row*ldc + bn + tx*4)      = make_uint2(packbf(l[0],l[1]), packbf(l[2],l[3]));
            *(uint2*)(Clo + (size_t)row*ldc + bn + 64 + tx*4) = make_uint2(packbf(l[4],l[5]), packbf(l[6],l[7]));
        }
    }
}

// ---------------- HMMA bf16 split GEMM (R8/R12-proven inner loop) ------------
// TERMS=3: (Ahi+Alo)@(Bhi+Blo)^T; TERMS=1: Ahi@Bhi^T only.
// OMODE: 0 fp32 out, 1 bf16 hi/lo split out, 2 bf16 hi only,
//        3 fused importance reduce: atomicAdd(Cf[row], sum_col relu(v)*iw3[col]),
//        4 fused max-pool over 16-row groups -> Cf[row/16 * ldc + col].
// RBMODE: 0 = none, 2 = generate rowbias from c4 @ iw1[768:772] in epilogue.
__device__ __forceinline__ void mma16816(float* c, const unsigned* a, unsigned b0, unsigned b1){
    asm volatile(
        "mma.sync.aligned.m16n8k16.row.col.f32.bf16.bf16.f32 "
        "{%0,%1,%2,%3}, {%4,%5,%6,%7}, {%8,%9}, {%0,%1,%2,%3};"
        : "+f"(c[0]), "+f"(c[1]), "+f"(c[2]), "+f"(c[3])
        : "r"(a[0]), "r"(a[1]), "r"(a[2]), "r"(a[3]), "r"(b0), "r"(b1));
}

template<bool RELU, int RBMODE, int OMODE, int TERMS>
__global__ __launch_bounds__(256,2) void hgemm(
    const __nv_bfloat16* __restrict__ Ahi, const __nv_bfloat16* __restrict__ Alo,
    const __nv_bfloat16* __restrict__ Bhi, const __nv_bfloat16* __restrict__ Blo,
    const float* __restrict__ bias,
    const float* __restrict__ c4g, const float* __restrict__ iw1g,
    const float* __restrict__ iw3g,
    __nv_bfloat16* __restrict__ Chi, __nv_bfloat16* __restrict__ Clo,
    float* __restrict__ Cf, int ldc, int K)
{
    __shared__ __nv_bfloat16 As[2][128][40];
    __shared__ __nv_bfloat16 Bs[2][128][40];
    const int tid  = threadIdx.x;
    const int wid  = tid >> 5, lane = tid & 31;
    const int g    = lane >> 2, tg = lane & 3;
    const int bm   = blockIdx.y * 128, bn = blockIdx.x * 128;
    const int wm   = (wid & 3) * 32, wn = (wid >> 2) * 64;
    const int rowA = tid >> 2;
    const int kq   = (tid & 3) * 8;

    const int nk  = K >> 5;
    const int nch = TERMS * nk;

    float acc[2][8][4];
    #pragma unroll
    for (int mi=0;mi<2;mi++)
        #pragma unroll
        for (int ni=0;ni<8;ni++)
            #pragma unroll
            for (int q=0;q<4;q++) acc[mi][ni][q] = 0.f;

    uint4 a0v,a1v,b0v,b1v;
    auto ldchunk = [&](int c){
        int term = c / nk, kc = c - term*nk;
        const __nv_bfloat16* Ab = (term<2) ? Ahi : Alo;
        const __nv_bfloat16* Bb = (term==1) ? Blo : Bhi;
        const __nv_bfloat16* ap = Ab + (size_t)(bm+rowA)*K + kc*32 + kq;
        const __nv_bfloat16* bp = Bb + (size_t)(bn+rowA)*K + kc*32 + kq;
        a0v = *(const uint4*)ap;  a1v = *(const uint4*)(ap + (size_t)64*K);
        b0v = *(const uint4*)bp;  b1v = *(const uint4*)(bp + (size_t)64*K);
    };
    auto stchunk = [&](int buf){
        *(uint4*)&As[buf][rowA][kq]    = a0v;
        *(uint4*)&As[buf][rowA+64][kq] = a1v;
        *(uint4*)&Bs[buf][rowA][kq]    = b0v;
        *(uint4*)&Bs[buf][rowA+64][kq] = b1v;
    };

    ldchunk(0); stchunk(0);
    __syncthreads();

    for (int c=0; c<nch; c++){
        const int buf = c & 1;
        const bool has = (c+1 < nch);
        if (has) ldchunk(c+1);
        #pragma unroll
        for (int kk=0; kk<32; kk+=16){
            unsigned af[2][4];
            #pragma unroll
            for (int mi=0;mi<2;mi++){
                const int rb0 = wm + mi*16 + g;
                af[mi][0] = *(const unsigned*)&As[buf][rb0  ][kk + tg*2];
                af[mi][1] = *(const unsigned*)&As[buf][rb0+8][kk + tg*2];
                af[mi][2] = *(const unsigned*)&As[buf][rb0  ][kk + 8 + tg*2];
                af[mi][3] = *(const unsigned*)&As[buf][rb0+8][kk + 8 + tg*2];
            }
            #pragma unroll
            for (int ni=0;ni<8;ni++){
                const int nr = wn + ni*8 + g;
                unsigned bw0 = *(const unsigned*)&Bs[buf][nr][kk + tg*2];
                unsigned bw1 = *(const unsigned*)&Bs[buf][nr][kk + 8 + tg*2];
                mma16816(acc[0][ni], af[0], bw0, bw1);
                mma16816(acc[1][ni], af[1], bw0, bw1);
            }
        }
        if (has) stchunk(buf ^ 1);
        __syncthreads();
    }

    // epilogue
    #pragma unroll
    for (int mi=0;mi<2;mi++){
        const int ra = bm + wm + mi*16 + g;
        const int rb_ = ra + 8;
        float4 ca, cb;
        if (RBMODE == 2){
            ca = *(const float4*)(c4g + (size_t)ra*4);
            cb = *(const float4*)(c4g + (size_t)rb_*4);
        }
        float pa = 0.f, pb = 0.f;   // OMODE 3 partials
        #pragma unroll
        for (int ni=0;ni<8;ni++){
            const int col = bn + wn + ni*8 + tg*2;
            float2 bv = *(const float2*)&bias[col];
            float v00 = acc[mi][ni][0] + bv.x, v01 = acc[mi][ni][1] + bv.y;
            float v10 = acc[mi][ni][2] + bv.x, v11 = acc[mi][ni][3] + bv.y;
            if (RBMODE == 2){
                float2 r0 = *(const float2*)(iw1g + (size_t)768*256 + col);
                float2 r1 = *(const float2*)(iw1g + (size_t)769*256 + col);
                float2 r2 = *(const float2*)(iw1g + (size_t)770*256 + col);
                float2 r3 = *(const float2*)(iw1g + (size_t)771*256 + col);
                v00 += ca.x*r0.x + ca.y*r1.x + ca.z*r2.x + ca.w*r3.x;
                v01 += ca.x*r0.y + ca.y*r1.y + ca.z*r2.y + ca.w*r3.y;
                v10 += cb.x*r0.x + cb.y*r1.x + cb.z*r2.x + cb.w*r3.x;
                v11 += cb.x*r0.y + cb.y*r1.y + cb.z*r2.y + cb.w*r3.y;
            }
            if (RELU){
                v00=fmaxf(v00,0.f); v01=fmaxf(v01,0.f);
                v10=fmaxf(v10,0.f); v11=fmaxf(v11,0.f);
            }
            if (OMODE == 0){
                *(float2*)&Cf[(size_t)ra*ldc + col]  = make_float2(v00,v01);
                *(float2*)&Cf[(size_t)rb_*ldc + col] = make_float2(v10,v11);
            } else if (OMODE == 2){
                *(unsigned*)&Chi[(size_t)ra*ldc + col]  = packbf(v00,v01);
                *(unsigned*)&Chi[(size_t)rb_*ldc + col] = packbf(v10,v11);
            } else if (OMODE == 3){
                float2 w3v = *(const float2*)&iw3g[col];
                pa += v00*w3v.x + v01*w3v.y;
                pb += v10*w3v.x + v11*w3v.y;
            } else if (OMODE == 4){
                // max over the warp's 16-row group: rows {g, g+8} per lane, then over g
                float m0 = fmaxf(v00, v10);
                float m1 = fmaxf(v01, v11);
                #pragma unroll
                for (int off=4; off<32; off<<=1){
                    m0 = fmaxf(m0, __shfl_xor_sync(0xffffffffu, m0, off));
                    m1 = fmaxf(m1, __shfl_xor_sync(0xffffffffu, m1, off));
                }
                if (g == 0){
                    const int tok = (bm + wm + mi*16) >> 4;
                    *(float2*)&Cf[(size_t)tok*ldc + col] = make_float2(m0, m1);
                }
            } else {
                float h00=__bfloat162float(__float2bfloat16(v00));
                float h01=__bfloat162float(__float2bfloat16(v01));
                float h10=__bfloat162float(__float2bfloat16(v10));
                float h11=__bfloat162float(__float2bfloat16(v11));
                *(unsigned*)&Chi[(size_t)ra*ldc + col]  = packbf(h00,h01);
                *(unsigned*)&Chi[(size_t)rb_*ldc + col] = packbf(h10,h11);
                *(unsigned*)&Clo[(size_t)ra*ldc + col]  = packbf(v00-h00, v01-h01);
                *(unsigned*)&Clo[(size_t)rb_*ldc + col] = packbf(v10-h10, v11-h11);
            }
        }
        if (OMODE == 3){
            pa += __shfl_xor_sync(0xffffffffu, pa, 1);
            pa += __shfl_xor_sync(0xffffffffu, pa, 2);
            pb += __shfl_xor_sync(0xffffffffu, pb, 1);
            pb += __shfl_xor_sync(0xffffffffu, pb, 2);
            if (tg == 0){
                atomicAdd(&Cf[ra], pa);
                atomicAdd(&Cf[rb_], pb);
            }
        }
    }
}

// ---------------- LayerNorm over rows of 256 ---------------------------------
// BIN: input bf16 (else fp32). LMODE: 0 fp32 out, 2 bf16 hi-only out
template<int LMODE, bool BIN>
__global__ void ln_kernel(const float* __restrict__ zf, const __nv_bfloat16* __restrict__ zb,
                          const float* __restrict__ gg, const float* __restrict__ bb,
                          __nv_bfloat16* __restrict__ oh, float* __restrict__ of)
{
    int row  = blockIdx.x*8 + (threadIdx.x>>5);
    int lane = threadIdx.x & 31;
    float v[8];
    if (BIN){
        uint4 p = *(const uint4*)(zb + (size_t)row*256 + lane*8);
        const unsigned w[4] = {p.x,p.y,p.z,p.w};
        #pragma unroll
        for (int q=0;q<4;q++){
            v[2*q]   = __bfloat162float(__ushort_as_bfloat16((unsigned short)(w[q] & 0xffffu)));
            v[2*q+1] = __bfloat162float(__ushort_as_bfloat16((unsigned short)(w[q] >> 16)));
        }
    } else {
        const float* rr = zf + (size_t)row*256 + lane*8;
        float4 p0 = *(const float4*)rr;
        float4 p1 = *(const float4*)(rr+4);
        v[0]=p0.x;v[1]=p0.y;v[2]=p0.z;v[3]=p0.w;v[4]=p1.x;v[5]=p1.y;v[6]=p1.z;v[7]=p1.w;
    }
    float s=0.f;
    #pragma unroll
    for (int j=0;j<8;j++) s+=v[j];
    #pragma unroll
    for (int off=16;off>0;off>>=1) s += __shfl_xor_sync(0xffffffffu, s, off);
    float mu = s * (1.f/256.f);
    float q=0.f;
    #pragma unroll
    for (int j=0;j<8;j++){ float d=v[j]-mu; q+=d*d; }
    #pragma unroll
    for (int off=16;off>0;off>>=1) q += __shfl_xor_sync(0xffffffffu, q, off);
    float inv = rsqrtf(q*(1.f/256.f) + 1e-5f);
    size_t off = (size_t)row*256 + lane*8;
    if (LMODE == 2){
        float h[8];
        #pragma unroll
        for (int j=0;j<8;j++)
            h[j] = (v[j]-mu)*inv*gg[lane*8+j] + bb[lane*8+j];
        *(uint4*)(oh+off) = make_uint4(packbf(h[0],h[1]),packbf(h[2],h[3]),packbf(h[4],h[5]),packbf(h[6],h[7]));
    } else {
        #pragma unroll
        for (int j=0;j<8;j++)
            of[off+j] = (v[j]-mu)*inv*gg[lane*8+j] + bb[lane*8+j];
    }
}

// ---------------- importance scalar (candidates only) -------------------------
__global__ void imp_kernel(const float* __restrict__ z, const float* __restrict__ iw3,
                           const float* __restrict__ ib3, float* __restrict__ imp)
{
    int row  = blockIdx.x*8 + (threadIdx.x>>5);
    int lane = threadIdx.x & 31;
    const float* r = z + (size_t)row*256 + lane*8;
    float s = 0.f;
    #pragma unroll
    for (int j=0;j<8;j++) s += r[j]*iw3[lane*8+j];
    #pragma unroll
    for (int off=16;off>0;off>>=1) s += __shfl_xor_sync(0xffffffffu, s, off);
    if (lane==0) imp[row] = s + ib3[0];
}

// ---------------- per-batch top-256 candidates (approx keys) ------------------
__global__ void topk256_kernel(const float* __restrict__ imp, const float* __restrict__ noise,
                               int* __restrict__ cand)
{
    extern __shared__ unsigned skey[];
    __shared__ unsigned hist[256];
    __shared__ unsigned s_prefix, s_mask;
    __shared__ int s_rem, s_cnt, s_eqcnt;
    __shared__ int eqbuf[512];
    const int b = blockIdx.x;
    const int tid = threadIdx.x;
    for (int i=tid;i<PB;i+=1024)
        skey[i] = f2u(imp[b*PB+i] + noise[b*PB+i]);
    if (tid==0){ s_prefix=0u; s_mask=0u; s_rem=KSEL; }
    __syncthreads();
    for (int round=0; round<4; round++){
        const int shift = 24 - 8*round;
        if (tid<256) hist[tid]=0u;
        __syncthreads();
        unsigned mask = s_mask, prefix = s_prefix;
        for (int i=tid;i<PB;i+=1024){
            unsigned k = skey[i];
            if ((k & mask) == prefix) atomicAdd(&hist[(k>>shift)&255u], 1u);
        }
        __syncthreads();
        if (tid==0){
            int rem = s_rem; unsigned cum=0; int bsel=0;
            for (int bin=255; bin>=0; bin--){
                if (cum + hist[bin] >= (unsigned)rem){ bsel=bin; break; }
                cum += hist[bin];
            }
            s_rem    = rem - (int)cum;
            s_prefix = prefix | ((unsigned)bsel << shift);
            s_mask   = mask   | (0xFFu << shift);
        }
        __syncthreads();
    }
    const unsigned kth = s_prefix;
    const int rEq = s_rem;
    if (tid==0){ s_cnt=0; s_eqcnt=0; }
    __syncthreads();
    for (int i=tid;i<PB;i+=1024){
        unsigned k = skey[i];
        if (k > kth){
            int p = atomicAdd(&s_cnt,1);
            cand[b*KSEL+p] = i;
        } else if (k == kth){
            int p = atomicAdd(&s_eqcnt,1);
            if (p < 512) eqbuf[p] = i;
        }
    }
    __syncthreads();
    if (tid==0){
        int base = s_cnt;
        for (int a=0;a<rEq;a++) cand[b*KSEL+base+a] = eqbuf[a];
    }
}

// ---------------- gather candidate inputs + compute rbc -----------------------
__global__ void cand_gather(const int* __restrict__ cand, const float* __restrict__ iw1,
                            float* __restrict__ xc, float* __restrict__ rbc)
{
    const int j = blockIdx.x;
    const int b = j >> 8;
    const int i = cand[j];
    const int gidx = b*PB + i;
    const int t = threadIdx.x;            // 64
    if (t < 2) ((float4*)xc)[j*2+t] = ((const float4*)g_x8)[(size_t)gidx*2+t];
    const int n = t*4;
    float4 c  = *(const float4*)(g_c4 + (size_t)gidx*4);
    float4 r0 = *(const float4*)(iw1 + (size_t)768*256 + n);
    float4 r1 = *(const float4*)(iw1 + (size_t)769*256 + n);
    float4 r2 = *(const float4*)(iw1 + (size_t)770*256 + n);
    float4 r3 = *(const float4*)(iw1 + (size_t)771*256 + n);
    float4 o;
    o.x = c.x*r0.x + c.y*r1.x + c.z*r2.x + c.w*r3.x;
    o.y = c.x*r0.y + c.y*r1.y + c.z*r2.y + c.w*r3.y;
    o.z = c.x*r0.z + c.y*r1.z + c.z*r2.z + c.w*r3.z;
    o.w = c.x*r0.w + c.y*r1.w + c.z*r2.w + c.w*r3.w;
    *(float4*)(rbc + (size_t)j*256 + n) = o;
}

// ---------------- exact top-128 among candidates ------------------------------
__global__ void topk_final(const float* __restrict__ impc, const float* __restrict__ noise,
                           const int* __restrict__ cand, const float* __restrict__ c4,
                           float* __restrict__ cent)
{
    __shared__ unsigned long long s[KSEL];
    const int b = blockIdx.x, t = threadIdx.x;
    const int i = cand[b*KSEL+t];
    float v = impc[b*KSEL+t] + noise[b*PB+i];
    s[t] = ((unsigned long long)(~f2u(v)) << 32) | (unsigned)i;
    __syncthreads();
    for (int ksz=2; ksz<=KSEL; ksz<<=1){
        for (int j=ksz>>1; j>0; j>>=1){
            int ixj = t ^ j;
            if (ixj > t){
                unsigned long long a = s[t], c = s[ixj];
                bool up = ((t & ksz) == 0);
                if (up ? (a > c) : (a < c)){ s[t]=c; s[ixj]=a; }
            }
            __syncthreads();
        }
    }
    if (t < MTOK){
        int i2 = (unsigned)(s[t] & 0xffffffffu);
        #pragma unroll
        for (int q=0;q<4;q++) cent[(b*MTOK+t)*4+q] = c4[(size_t)(b*PB+i2)*4+q];
    }
}

// ---------------- stable sort of 128 cents by t -------------------------------
__global__ void sortt_kernel(const float* __restrict__ cent, int* __restrict__ order)
{
    __shared__ unsigned long long s[128];
    const int b = blockIdx.x, tid = threadIdx.x;
    float t = cent[(b*MTOK+tid)*4+3];
    s[tid] = ((unsigned long long)f2u(t) << 32) | (unsigned)tid;
    __syncthreads();
    for (int ksz=2; ksz<=128; ksz<<=1){
        for (int j=ksz>>1; j>0; j>>=1){
            int ixj = tid ^ j;
            if (ixj > tid){
                unsigned long long a = s[tid], c = s[ixj];
                bool up = ((tid & ksz) == 0);
                if (up ? (a > c) : (a < c)){ s[tid]=c; s[ixj]=a; }
            }
            __syncthreads();
        }
    }
    order[b*MTOK+tid] = (int)(s[tid] & 0xffffffffu);
}

// ---------------- brute-force 16-NN -------------------------------------------
__global__ void knn_kernel(const float* __restrict__ c4, const float* __restrict__ cent,
                           int* __restrict__ knn)
{
    __shared__ unsigned long long lists[128][KNN];
    const int bm = blockIdx.x;
    const int b  = bm >> 7;
    const int tid = threadIdx.x;
    const float cx = cent[bm*4+0], cy = cent[bm*4+1], cz = cent[bm*4+2], ct = cent[bm*4+3];
    unsigned long long loc[KNN];
    #pragma unroll
    for (int q=0;q<KNN;q++) loc[q] = ~0ull;
    const float* cb = c4 + (size_t)b*PB*4;
    for (int i=tid;i<PB;i+=128){
        float4 p = *(const float4*)(cb + (size_t)i*4);
        float dx=p.x-cx, dy=p.y-cy, dz=p.z-cz, dt=p.w-ct;
        float d2 = dx*dx + dy*dy + dz*dz + dt*dt;
        unsigned long long key = ((unsigned long long)(__float_as_uint(d2)|0x80000000u) << 32) | (unsigned)i;
        if (key < loc[KNN-1]){
            loc[KNN-1] = key;
            #pragma unroll
            for (int q=KNN-1;q>0;q--){
                if (loc[q] < loc[q-1]){ unsigned long long t=loc[q]; loc[q]=loc[q-1]; loc[q-1]=t; }
            }
        }
    }
    #pragma unroll
    for (int q=0;q<KNN;q++) lists[tid][q]=loc[q];
    __syncthreads();
    for (int sgap=64; sgap>0; sgap>>=1){
        if (tid < sgap){
            unsigned long long out[KNN];
            int i1=0, i2=0;
            #pragma unroll
            for (int q=0;q<KNN;q++){
                unsigned long long a=lists[tid][i1], c=lists[tid+sgap][i2];
                if (a<=c){ out[q]=a; i1++; } else { out[q]=c; i2++; }
            }
            #pragma unroll
            for (int q=0;q<KNN;q++) lists[tid][q]=out[q];
        }
        __syncthreads();
    }
    if (tid < KNN) knn[bm*KNN+tid] = (int)(lists[0][tid] & 0xffffffffu);
}

// ---------------- gather x8 rows of knn neighbors -----------------------------
__global__ void gatherx_kernel(const int* __restrict__ knn, float* __restrict__ gx)
{
    const int r = blockIdx.x*256 + threadIdx.x;   // 0..NGATH-1
    const int bm = r / KNN;
    const int b  = bm >> 7;
    const int nb = b*PB + knn[r];
    ((float4*)gx)[(size_t)r*2+0] = ((const float4*)g_x8)[(size_t)nb*2+0];
    ((float4*)gx)[(size_t)r*2+1] = ((const float4*)g_x8)[(size_t)nb*2+1];
}

// ---------------- scatter to output in time order -----------------------------
__global__ void out_kernel(const float* __restrict__ tok, const float* __restrict__ cent,
                           const int* __restrict__ order, float* __restrict__ out)
{
    const int bj = blockIdx.x;
    const int b  = bj >> 7;
    const int o  = order[bj];
    const float* src = tok + (size_t)(b*MTOK+o)*TOKD;
    float* dst = out + (size_t)bj*TOKD;
    for (int c=threadIdx.x;c<TOKD;c+=256) dst[c]=src[c];
    if (threadIdx.x < 4) out[(size_t)BATCH*MTOK*TOKD + bj*4 + threadIdx.x] = cent[(b*MTOK+o)*4+threadIdx.x];
    if (threadIdx.x == 4) out[(size_t)BATCH*MTOK*TOKD + (size_t)BATCH*MTOK*4 + bj] = 1.0f;
}

// ---------------- launch ------------------------------------------------------
extern "C" void kernel_launch(void* const* d_in, const int* in_sizes, int n_in,
                              void* d_out, int out_size)
{
    (void)in_sizes; (void)n_in; (void)out_size;
    const float* coords = (const float*)d_in[0];
    const float* feats  = (const float*)d_in[1];
    const float* w1  = (const float*)d_in[3];  const float* b1  = (const float*)d_in[4];
    const float* w2  = (const float*)d_in[5];  const float* b2  = (const float*)d_in[6];
    const float* w3  = (const float*)d_in[7];  const float* b3  = (const float*)d_in[8];
    const float* w4  = (const float*)d_in[9];  const float* b4  = (const float*)d_in[10];
    const float* iw1 = (const float*)d_in[11]; const float* ib1 = (const float*)d_in[12];
    const float* lng = (const float*)d_in[13]; const float* lnb = (const float*)d_in[14];
    const float* iw2 = (const float*)d_in[15]; const float* ib2 = (const float*)d_in[16];
    const float* iw3 = (const float*)d_in[17]; const float* ib3 = (const float*)d_in[18];
    const float* nw1 = (const float*)d_in[19]; const float* nb1 = (const float*)d_in[20];
    const float* nw2 = (const float*)d_in[21]; const float* nb2 = (const float*)d_in[22];
    const float* noise = (const float*)d_in[23];

    void *px8,*pw1p,*pc4,*ph1h,*ph2h,*ph3h,*pwp,*pbp,*pz0;
    void *pz1h,*pz2h,*pimp,*pcand,*pxc,*prbc,*ph1c,*ph2c,*ph3c,*pz1c,*pz2c,*pz3c,*pimpc;
    void *pcent,*pord,*pknn,*pgx,*ph1gh,*ph1gl,*ph2gh,*ph2gl,*pgh,*pgl,*ppool,*pt1,*ptok;
    void *pw2h,*pw2l,*pw3h,*pw3l,*pw4h,*pw4l,*pwph,*pwpl,*piw2h,*piw2l;
    cudaGetSymbolAddress(&px8,g_x8);     cudaGetSymbolAddress(&pw1p,g_w1p);
    cudaGetSymbolAddress(&pc4,g_c4);
    cudaGetSymbolAddress(&ph1h,g_h1h);
    cudaGetSymbolAddress(&ph2h,g_h2h);   cudaGetSymbolAddress(&ph3h,g_h3h);
    cudaGetSymbolAddress(&pwp,g_wp);     cudaGetSymbolAddress(&pbp,g_biasp);
    cudaGetSymbolAddress(&pz0,g_zero256);
    cudaGetSymbolAddress(&pz1h,g_z1h);   cudaGetSymbolAddress(&pz2h,g_z2h);
    cudaGetSymbolAddress(&pimp,g_imp);   cudaGetSymbolAddress(&pcand,g_cand);
    cudaGetSymbolAddress(&pxc,g_xc);     cudaGetSymbolAddress(&prbc,g_rbc);
    cudaGetSymbolAddress(&ph1c,g_h1c);   cudaGetSymbolAddress(&ph2c,g_h2c);
    cudaGetSymbolAddress(&ph3c,g_h3c);   cudaGetSymbolAddress(&pz1c,g_z1c);
    cudaGetSymbolAddress(&pz2c,g_z2c);   cudaGetSymbolAddress(&pz3c,g_z3c);
    cudaGetSymbolAddress(&pimpc,g_impc);
    cudaGetSymbolAddress(&pcent,g_cent); cudaGetSymbolAddress(&pord,g_order);
    cudaGetSymbolAddress(&pknn,g_knn);   cudaGetSymbolAddress(&pgx,g_gx);
    cudaGetSymbolAddress(&ph1gh,g_h1gh); cudaGetSymbolAddress(&ph1gl,g_h1gl);
    cudaGetSymbolAddress(&ph2gh,g_h2gh); cudaGetSymbolAddress(&ph2gl,g_h2gl);
    cudaGetSymbolAddress(&pgh,g_gh);     cudaGetSymbolAddress(&pgl,g_gl);
    cudaGetSymbolAddress(&ppool,g_pooled);
    cudaGetSymbolAddress(&pt1,g_t1);     cudaGetSymbolAddress(&ptok,g_tok);
    cudaGetSymbolAddress(&pw2h,g_w2th);  cudaGetSymbolAddress(&pw2l,g_w2tl);
    cudaGetSymbolAddress(&pw3h,g_w3th);  cudaGetSymbolAddress(&pw3l,g_w3tl);
    cudaGetSymbolAddress(&pw4h,g_w4th);  cudaGetSymbolAddress(&pw4l,g_w4tl);
    cudaGetSymbolAddress(&pwph,g_wpth);  cudaGetSymbolAddress(&pwpl,g_wptl);
    cudaGetSymbolAddress(&piw2h,g_iw2th);cudaGetSymbolAddress(&piw2l,g_iw2tl);

    cudaFuncSetAttribute(topk256_kernel, cudaFuncAttributeMaxDynamicSharedMemorySize, PB*4);

    prep_points<<<NPTS/256, 256>>>(coords, feats);
    prep_w<<<8, 256>>>(w1);
    biasp_init<<<1,256>>>(ib1, (float*)pbp);
    biasp_acc<<<8,256>>>(b4, iw1, (float*)pbp);
    init_imp<<<NPTS/256,256>>>(ib3, (float*)pimp);
    sgemm128<false,false,0><<<dim3(2,6),256>>>(w4, 768, iw1, 256, (const float*)pz0,
        nullptr, (float*)pwp, nullptr, nullptr, 256, 768);
    conv_wt<<<(512*256+255)/256,256>>>(w2, 256, 512, (__nv_bfloat16*)pw2h, (__nv_bfloat16*)pw2l);
    conv_wt<<<(768*512+255)/256,256>>>(w3, 512, 768, (__nv_bfloat16*)pw3h, (__nv_bfloat16*)pw3l);
    conv_wt<<<(768*768+255)/256,256>>>(w4, 768, 768, (__nv_bfloat16*)pw4h, (__nv_bfloat16*)pw4l);
    conv_wt<<<(256*768+255)/256,256>>>((const float*)pwp, 768, 256, (__nv_bfloat16*)pwph, (__nv_bfloat16*)pwpl);
    conv_wt<<<(256*256+255)/256,256>>>(iw2, 256, 256, (__nv_bfloat16*)piw2h, (__nv_bfloat16*)piw2l);

    // L1 scalar -> h1 hi-only (full points; 1-term trunk never reads lo)
    sgemm128<true,false,2><<<dim3(2,1024),256>>>((const float*)px8, 8, (const float*)pw1p, 256, b1,
        nullptr, nullptr, (__nv_bfloat16*)ph1h, nullptr, 256, 8);
    // trunk 1-term (importance-only precision), bf16-hi outputs
    hgemm<true,0,2,1><<<dim3(4,1024),256>>>((const __nv_bfloat16*)ph1h, nullptr,
        (const __nv_bfloat16*)pw2h,(const __nv_bfloat16*)pw2l, b2, nullptr, nullptr, nullptr,
        (__nv_bfloat16*)ph2h, nullptr, nullptr, 512, 256);
    hgemm<true,0,2,1><<<dim3(6,1024),256>>>((const __nv_bfloat16*)ph2h, nullptr,
        (const __nv_bfloat16*)pw3h,(const __nv_bfloat16*)pw3l, b3, nullptr, nullptr, nullptr,
        (__nv_bfloat16*)ph3h, nullptr, nullptr, 768, 512);
    // importance branch (1-term) with epilogue rowbias; z1 stored bf16 hi-only
    hgemm<true,2,2,1><<<dim3(2,1024),256>>>((const __nv_bfloat16*)ph3h, nullptr,
        (const __nv_bfloat16*)pwph,(const __nv_bfloat16*)pwpl, (const float*)pbp,
        (const float*)pc4, iw1, nullptr,
        (__nv_bfloat16*)pz1h, nullptr, nullptr, 256, 768);
    ln_kernel<2,true><<<NPTS/8,256>>>(nullptr, (const __nv_bfloat16*)pz1h, lng, lnb,
        (__nv_bfloat16*)pz2h, nullptr);
    // iw2 GEMM with fused importance reduce (z3 never materialized)
    hgemm<true,0,3,1><<<dim3(2,1024),256>>>((const __nv_bfloat16*)pz2h, nullptr,
        (const __nv_bfloat16*)piw2h,(const __nv_bfloat16*)piw2l, ib2, nullptr, nullptr, iw3,
        nullptr, nullptr, (float*)pimp, 256, 256);

    // approx top-256 candidates, then exact scalar refinement
    topk256_kernel<<<BATCH,1024,PB*4>>>((const float*)pimp, noise, (int*)pcand);
    cand_gather<<<NCAND,64>>>((const int*)pcand, iw1, (float*)pxc, (float*)prbc);
    sgemm128<true,false,0><<<dim3(2,16),256>>>((const float*)pxc, 8, (const float*)pw1p, 256, b1,
        nullptr, (float*)ph1c, nullptr, nullptr, 256, 8);
    sgemm128<true,false,0><<<dim3(4,16),256>>>((const float*)ph1c, 256, w2, 512, b2,
        nullptr, (float*)ph2c, nullptr, nullptr, 512, 256);
    sgemm128<true,false,0><<<dim3(6,16),256>>>((const float*)ph2c, 512, w3, 768, b3,
        nullptr, (float*)ph3c, nullptr, nullptr, 768, 512);
    sgemm128<true,true,0><<<dim3(2,16),256>>>((const float*)ph3c, 768, (const float*)pwp, 256,
        (const float*)pbp, (const float*)prbc, (float*)pz1c, nullptr, nullptr, 256, 768);
    ln_kernel<0,false><<<NCAND/8,256>>>((const float*)pz1c, nullptr, lng, lnb, nullptr, (float*)pz2c);
    sgemm128<true,false,0><<<dim3(2,16),256>>>((const float*)pz2c, 256, iw2, 256, ib2,
        nullptr, (float*)pz3c, nullptr, nullptr, 256, 256);
    imp_kernel<<<NCAND/8,256>>>((const float*)pz3c, iw3, ib3, (float*)pimpc);
    topk_final<<<BATCH,KSEL>>>((const float*)pimpc, noise, (const int*)pcand,
                               (const float*)pc4, (float*)pcent);

    // neighborhoods (coordinates only)
    sortt_kernel<<<BATCH,128>>>((const float*)pcent, (int*)pord);
    knn_kernel<<<BATCH*MTOK,128>>>((const float*)pc4, (const float*)pcent, (int*)pknn);

    // neighbor trunk recompute at full (3-term) precision: 16384 rows
    gatherx_kernel<<<NGATH/256,256>>>((const int*)pknn, (float*)pgx);
    sgemm128<true,false,1><<<dim3(2,NGATH/128),256>>>((const float*)pgx, 8, (const float*)pw1p, 256, b1,
        nullptr, nullptr, (__nv_bfloat16*)ph1gh, (__nv_bfloat16*)ph1gl, 256, 8);
    hgemm<true,0,1,3><<<dim3(4,NGATH/128),256>>>((const __nv_bfloat16*)ph1gh,(const __nv_bfloat16*)ph1gl,
        (const __nv_bfloat16*)pw2h,(const __nv_bfloat16*)pw2l, b2, nullptr, nullptr, nullptr,
        (__nv_bfloat16*)ph2gh,(__nv_bfloat16*)ph2gl, nullptr, 512, 256);
    hgemm<true,0,1,3><<<dim3(6,NGATH/128),256>>>((const __nv_bfloat16*)ph2gh,(const __nv_bfloat16*)ph2gl,
        (const __nv_bfloat16*)pw3h,(const __nv_bfloat16*)pw3l, b3, nullptr, nullptr, nullptr,
        (__nv_bfloat16*)pgh,(__nv_bfloat16*)pgl, nullptr, 768, 512);
    // pf GEMM with fused max-pool over 16-row KNN groups -> pooled
    hgemm<false,0,4,3><<<dim3(6,NGATH/128),256>>>((const __nv_bfloat16*)pgh,(const __nv_bfloat16*)pgl,
        (const __nv_bfloat16*)pw4h,(const __nv_bfloat16*)pw4l, b4, nullptr, nullptr, nullptr,
        nullptr, nullptr, (float*)ppool, 768, 768);

    // token MLP scalar fp32
    sgemm128<true ,false,0><<<dim3(6,8),256>>>((const float*)ppool, 768, nw1, 768, nb1,
        nullptr, (float*)pt1, nullptr, nullptr, 768, 768);
    sgemm128<false,false,0><<<dim3(6,8),256>>>((const float*)pt1, 768, nw2, 768, nb2,
        nullptr, (float*)ptok, nullptr, nullptr, 768, 768);

    out_kernel<<<BATCH*MTOK,256>>>((const float*)ptok, (const float*)pcent, (const int*)pord, (float*)d_out);
}